// round 3
// baseline (speedup 1.0000x reference)
#include <cuda_runtime.h>
#include <math.h>

#define Bb 32
#define Nn 1024
#define Cc 768
#define Mm 64
#define Hh 12
#define Dd 64

// Scratch (allocation-free contract: __device__ globals)
__device__ float g_ct[Bb * Nn * Mm];   // (B, N, M)  cluster weights (sigmoid/N)
__device__ float g_z [Bb * Mm * Cc];   // (B, M, C)  cluster centers (L2-normed)
__device__ float g_q [Bb * Nn * Cc];   // (B, N, C)
__device__ float g_k [Bb * Mm * Cc];
__device__ float g_v [Bb * Mm * Cc];
__device__ float g_o [Bb * Nn * Cc];

// ---------------------------------------------------------------------------
// GEMM NT: C[i,j] = sum_k A[i,k] * B[j,k]  (+bias[j], optional sigmoid/N)
// A: (I,K) row-major, B: (J,K) row-major (i.e. x @ W^T with W=[out,in]).
// I%64==0, J%64==0, K%16==0 guaranteed by caller.
// ---------------------------------------------------------------------------
__global__ __launch_bounds__(256) void gemm_nt(
    const float* __restrict__ A, const float* __restrict__ Bw,
    const float* __restrict__ bias, float* __restrict__ Cm,
    int I, int J, int K, int mode)
{
    __shared__ float As[16][65];
    __shared__ float Bs[16][65];
    const int tid = threadIdx.x;
    const int i0 = blockIdx.y * 64;
    const int j0 = blockIdx.x * 64;
    const int tx = tid & 15, ty = tid >> 4;
    const int lr = tid >> 2;          // 0..63 row within tile
    const int lc = (tid & 3) << 2;    // 0,4,8,12 k-offset

    float acc[4][4];
#pragma unroll
    for (int r = 0; r < 4; r++)
#pragma unroll
        for (int c = 0; c < 4; c++) acc[r][c] = 0.f;

    const float* Ap = A + (long)(i0 + lr) * K + lc;
    const float* Bp = Bw + (long)(j0 + lr) * K + lc;

    for (int k0 = 0; k0 < K; k0 += 16) {
        float4 a = *(const float4*)(Ap + k0);
        float4 b = *(const float4*)(Bp + k0);
        As[lc + 0][lr] = a.x; As[lc + 1][lr] = a.y;
        As[lc + 2][lr] = a.z; As[lc + 3][lr] = a.w;
        Bs[lc + 0][lr] = b.x; Bs[lc + 1][lr] = b.y;
        Bs[lc + 2][lr] = b.z; Bs[lc + 3][lr] = b.w;
        __syncthreads();
#pragma unroll
        for (int kk = 0; kk < 16; kk++) {
            float av[4], bv[4];
#pragma unroll
            for (int r = 0; r < 4; r++) av[r] = As[kk][ty * 4 + r];
#pragma unroll
            for (int c = 0; c < 4; c++) bv[c] = Bs[kk][tx * 4 + c];
#pragma unroll
            for (int r = 0; r < 4; r++)
#pragma unroll
                for (int c = 0; c < 4; c++) acc[r][c] += av[r] * bv[c];
        }
        __syncthreads();
    }

#pragma unroll
    for (int r = 0; r < 4; r++) {
        const int i = i0 + ty * 4 + r;
#pragma unroll
        for (int c = 0; c < 4; c++) {
            const int j = j0 + tx * 4 + c;
            float val = acc[r][c];
            if (bias) val += bias[j];
            if (mode == 1) {
                // sigmoid(val) / N
                val = (1.f / (1.f + expf(-val))) * (1.f / (float)Nn);
            }
            Cm[(long)i * J + j] = val;
        }
    }
}

// ---------------------------------------------------------------------------
// GEMM TN (batched): C[i,j] = sum_k A[k,i] * B[k,j]
// A: (K, I) ld=lda ; B: (K, J) ld=ldb ; C: (I, J) ld=ldc. Per-batch strides.
// Used for z[b] = ct[b]^T @ x[b]   (I=64, J=768, K=1024)
// ---------------------------------------------------------------------------
__global__ __launch_bounds__(256) void gemm_tn(
    const float* __restrict__ A, const float* __restrict__ Bx,
    float* __restrict__ Cm,
    int I, int J, int K, int lda, int ldb, int ldc,
    long sA, long sB, long sC)
{
    A  += (long)blockIdx.z * sA;
    Bx += (long)blockIdx.z * sB;
    Cm += (long)blockIdx.z * sC;

    __shared__ float As[16][64];
    __shared__ float Bs[16][64];
    const int tid = threadIdx.x;
    const int i0 = blockIdx.y * 64;
    const int j0 = blockIdx.x * 64;
    const int tx = tid & 15, ty = tid >> 4;
    const int kr = tid >> 4;          // 0..15 (k row)
    const int ic = (tid & 15) << 2;   // 0..60 step 4

    float acc[4][4];
#pragma unroll
    for (int r = 0; r < 4; r++)
#pragma unroll
        for (int c = 0; c < 4; c++) acc[r][c] = 0.f;

    for (int k0 = 0; k0 < K; k0 += 16) {
        *(float4*)&As[kr][ic] = *(const float4*)(A  + (long)(k0 + kr) * lda + i0 + ic);
        *(float4*)&Bs[kr][ic] = *(const float4*)(Bx + (long)(k0 + kr) * ldb + j0 + ic);
        __syncthreads();
#pragma unroll
        for (int kk = 0; kk < 16; kk++) {
            float av[4], bv[4];
#pragma unroll
            for (int r = 0; r < 4; r++) av[r] = As[kk][ty * 4 + r];
#pragma unroll
            for (int c = 0; c < 4; c++) bv[c] = Bs[kk][tx * 4 + c];
#pragma unroll
            for (int r = 0; r < 4; r++)
#pragma unroll
                for (int c = 0; c < 4; c++) acc[r][c] += av[r] * bv[c];
        }
        __syncthreads();
    }

#pragma unroll
    for (int r = 0; r < 4; r++) {
        const int i = i0 + ty * 4 + r;
#pragma unroll
        for (int c = 0; c < 4; c++) {
            const int j = j0 + tx * 4 + c;
            Cm[(long)i * ldc + j] = acc[r][c];
        }
    }
}

// ---------------------------------------------------------------------------
// L2-normalize rows of z: z[row,:] /= max(||z[row,:]||, 1e-12)
// ---------------------------------------------------------------------------
__global__ __launch_bounds__(256) void l2norm(float* __restrict__ z)
{
    const int row = blockIdx.x;
    float* p = z + (long)row * Cc;
    float s = 0.f;
    for (int c = threadIdx.x; c < Cc; c += 256) {
        float v = p[c];
        s += v * v;
    }
    __shared__ float red[256];
    red[threadIdx.x] = s;
    __syncthreads();
    for (int st = 128; st > 0; st >>= 1) {
        if (threadIdx.x < st) red[threadIdx.x] += red[threadIdx.x + st];
        __syncthreads();
    }
    const float norm = sqrtf(red[0]);
    const float inv = 1.f / fmaxf(norm, 1e-12f);
    for (int c = threadIdx.x; c < Cc; c += 256) p[c] *= inv;
}

// ---------------------------------------------------------------------------
// Fused attention: per (b,h), M=64 keys, D=64.
// One thread per query row n, online softmax, K/V head staged in smem.
// grid (B*H, N/128), block 128.
// ---------------------------------------------------------------------------
__global__ __launch_bounds__(128) void attn_kernel(
    const float* __restrict__ q, const float* __restrict__ k,
    const float* __restrict__ v, float* __restrict__ o)
{
    const int bh = blockIdx.x;
    const int b = bh / Hh;
    const int h = bh % Hh;
    const int n = blockIdx.y * 128 + threadIdx.x;

    __shared__ float ks[Mm][Dd];
    __shared__ float vs[Mm][Dd];

    // stage K,V head tiles (64x64 each)
    for (int idx = threadIdx.x; idx < Mm * (Dd / 4); idx += 128) {
        const int m = idx >> 4;
        const int d4 = (idx & 15) << 2;
        const long base = ((long)b * Mm + m) * Cc + h * Dd + d4;
        *(float4*)&ks[m][d4] = *(const float4*)&k[base];
        *(float4*)&vs[m][d4] = *(const float4*)&v[base];
    }
    __syncthreads();

    float qd[Dd];
    const float* qp = q + ((long)b * Nn + n) * Cc + h * Dd;
#pragma unroll
    for (int d4 = 0; d4 < Dd; d4 += 4) {
        float4 t = *(const float4*)(qp + d4);
        qd[d4 + 0] = t.x; qd[d4 + 1] = t.y; qd[d4 + 2] = t.z; qd[d4 + 3] = t.w;
    }

    float oacc[Dd];
#pragma unroll
    for (int d = 0; d < Dd; d++) oacc[d] = 0.f;

    float mmax = -1e30f, lsum = 0.f;
    const float scale = 0.125f;  // D^-0.5, D=64

    for (int m = 0; m < Mm; m++) {
        float s = 0.f;
#pragma unroll
        for (int d = 0; d < Dd; d++) s += qd[d] * ks[m][d];
        s *= scale;
        const float nm = fmaxf(mmax, s);
        const float corr = __expf(mmax - nm);
        const float p = __expf(s - nm);
        lsum = lsum * corr + p;
#pragma unroll
        for (int d = 0; d < Dd; d++) oacc[d] = oacc[d] * corr + p * vs[m][d];
        mmax = nm;
    }

    const float inv = 1.f / lsum;
    float* op = o + ((long)b * Nn + n) * Cc + h * Dd;
#pragma unroll
    for (int d4 = 0; d4 < Dd; d4 += 4) {
        float4 t;
        t.x = oacc[d4 + 0] * inv; t.y = oacc[d4 + 1] * inv;
        t.z = oacc[d4 + 2] * inv; t.w = oacc[d4 + 3] * inv;
        *(float4*)(op + d4) = t;
    }
}

// ---------------------------------------------------------------------------
extern "C" void kernel_launch(void* const* d_in, const int* in_sizes, int n_in,
                              void* d_out, int out_size)
{
    (void)in_sizes; (void)n_in; (void)out_size;
    const float* x  = (const float*)d_in[0];
    const float* Wc = (const float*)d_in[1];
    const float* bc = (const float*)d_in[2];
    const float* Wq = (const float*)d_in[3];
    const float* bq = (const float*)d_in[4];
    const float* Wk = (const float*)d_in[5];
    const float* bk = (const float*)d_in[6];
    const float* Wv = (const float*)d_in[7];
    const float* bv = (const float*)d_in[8];
    const float* Wp = (const float*)d_in[9];
    const float* bp = (const float*)d_in[10];
    float* out = (float*)d_out;

    float *ct, *z, *q, *k, *v, *o;
    cudaGetSymbolAddress((void**)&ct, g_ct);
    cudaGetSymbolAddress((void**)&z,  g_z);
    cudaGetSymbolAddress((void**)&q,  g_q);
    cudaGetSymbolAddress((void**)&k,  g_k);
    cudaGetSymbolAddress((void**)&v,  g_v);
    cudaGetSymbolAddress((void**)&o,  g_o);

    const int IN = Bb * Nn;   // 32768
    const int IM = Bb * Mm;   // 2048

    // 1. cluster logits: ct(B*N, M) = sigmoid(x @ Wc^T + bc) / N
    gemm_nt<<<dim3(Mm / 64, IN / 64), 256>>>(x, Wc, bc, ct, IN, Mm, Cc, 1);

    // 2. z[b] = ct[b]^T @ x[b]   (64 x 768, K=1024)
    gemm_tn<<<dim3(Cc / 64, Mm / 64, Bb), 256>>>(
        ct, x, z, Mm, Cc, Nn, Mm, Cc, Cc,
        (long)Nn * Mm, (long)Nn * Cc, (long)Mm * Cc);

    // 3. L2 normalize z rows
    l2norm<<<IM, 256>>>(z);

    // 4. Q = x @ Wq^T + bq
    gemm_nt<<<dim3(Cc / 64, IN / 64), 256>>>(x, Wq, bq, q, IN, Cc, Cc, 0);

    // 5. K = z @ Wk^T + bk ; 6. V = z @ Wv^T + bv
    gemm_nt<<<dim3(Cc / 64, IM / 64), 256>>>(z, Wk, bk, k, IM, Cc, Cc, 0);
    gemm_nt<<<dim3(Cc / 64, IM / 64), 256>>>(z, Wv, bv, v, IM, Cc, Cc, 0);

    // 7. fused attention -> o (B, N, C)
    attn_kernel<<<dim3(Bb * Hh, Nn / 128), 128>>>(q, k, v, o);

    // 8. out = o @ Wp^T + bp
    gemm_nt<<<dim3(Cc / 64, IN / 64), 256>>>(o, Wp, bp, out, IN, Cc, Cc, 0);
}

// round 6
// speedup vs baseline: 2.4958x; 2.4958x over previous
#include <cuda_runtime.h>
#include <cuda_bf16.h>
#include <math.h>
#include <stdint.h>

#define Bb 32
#define Nn 1024
#define Cc 768
#define Mm 64
#define Hh 12
#define Dd 64

// ---------------- scratch (__device__ globals per allocation contract) ------
__device__ float g_ct[Bb * Nn * Mm];
__device__ float g_z [Bb * Mm * Cc];
__device__ float g_q [Bb * Nn * Cc];
__device__ float g_k [Bb * Mm * Cc];
__device__ float g_v [Bb * Mm * Cc];

__device__ __nv_bfloat16 g_xh[Bb * Nn * Cc], g_xl[Bb * Nn * Cc];
__device__ __nv_bfloat16 g_oh[Bb * Nn * Cc], g_ol[Bb * Nn * Cc];
__device__ __nv_bfloat16 g_zh[Bb * Mm * Cc], g_zl[Bb * Mm * Cc];
#define W_OFF_C 0
#define W_OFF_Q (Mm * Cc)
#define W_OFF_K (W_OFF_Q + Cc * Cc)
#define W_OFF_V (W_OFF_K + Cc * Cc)
#define W_OFF_P (W_OFF_V + Cc * Cc)
#define W_TOTAL (W_OFF_P + Cc * Cc)
__device__ __nv_bfloat16 g_wh[W_TOTAL], g_wl[W_TOTAL];

// ---------------- helpers ---------------------------------------------------
__device__ __forceinline__ uint32_t smem_u32(const void* p) {
    uint32_t a;
    asm("{ .reg .u64 t; cvta.to.shared.u64 t, %1; cvt.u32.u64 %0, t; }"
        : "=r"(a) : "l"(p));
    return a;
}
#define CP16(saddr, gaddr) \
    asm volatile("cp.async.cg.shared.global [%0], [%1], 16;" \
                 :: "r"(saddr), "l"(gaddr))
#define CP_COMMIT() asm volatile("cp.async.commit_group;")
#define CP_WAIT(n)  asm volatile("cp.async.wait_group %0;" :: "n"(n))

#define LDSM4(r, a) \
    asm volatile("ldmatrix.sync.aligned.m8n8.x4.shared.b16 {%0,%1,%2,%3}, [%4];" \
        : "=r"((r)[0]), "=r"((r)[1]), "=r"((r)[2]), "=r"((r)[3]) : "r"(a))

#define MMA_BF16(c, a, b0, b1) \
    asm volatile("mma.sync.aligned.m16n8k16.row.col.f32.bf16.bf16.f32 " \
        "{%0,%1,%2,%3},{%4,%5,%6,%7},{%8,%9},{%0,%1,%2,%3};" \
        : "+f"((c)[0]), "+f"((c)[1]), "+f"((c)[2]), "+f"((c)[3]) \
        : "r"((a)[0]), "r"((a)[1]), "r"((a)[2]), "r"((a)[3]), "r"(b0), "r"(b1))

__device__ __forceinline__ void split2(float a, float b, uint32_t& hi, uint32_t& lo) {
    __nv_bfloat16 ha = __float2bfloat16(a), hb = __float2bfloat16(b);
    float ra = a - __bfloat162float(ha);
    float rb = b - __bfloat162float(hb);
    __nv_bfloat162 H, L;
    H.x = ha; H.y = hb;
    L.x = __float2bfloat16(ra); L.y = __float2bfloat16(rb);
    hi = *(uint32_t*)&H; lo = *(uint32_t*)&L;
}

// ---------------- fp32 -> bf16 hi/lo split converter ------------------------
__global__ __launch_bounds__(256) void cvt_hl(const float4* __restrict__ in,
                                              uint2* __restrict__ hi,
                                              uint2* __restrict__ lo, int n4) {
    int i = blockIdx.x * 256 + threadIdx.x;
    if (i >= n4) return;
    float4 a = in[i];
    uint32_t h0, l0, h1, l1;
    split2(a.x, a.y, h0, l0);
    split2(a.z, a.w, h1, l1);
    hi[i] = make_uint2(h0, h1);
    lo[i] = make_uint2(l0, l1);
}

// ---------------- split-bf16 GEMM NT via mma.sync ---------------------------
// C(I,J) = A(I,768)·B(J,768)^T + bias [, sigmoid/N]. Block 128 x TN, 8 warps.
// Warp grid 2(M) x 4(N); warp tile 64 x TN/4. K chunks of 32, cp.async 2-stage.
// SMEM rows: 64B (32 bf16); 16B chunk c of row r stored at c ^ ((r>>1)&3).
template <int TN, int MODE>
__global__ __launch_bounds__(256) void gemm_tc(
    const __nv_bfloat16* __restrict__ Ah, const __nv_bfloat16* __restrict__ Al,
    const __nv_bfloat16* __restrict__ Bh, const __nv_bfloat16* __restrict__ Bl,
    const float* __restrict__ bias, float* __restrict__ Cout, int J)
{
    constexpr int K = Cc;              // 768
    constexpr int KC = 32;             // k per chunk
    constexpr int NCH = K / KC;        // 24
    constexpr int ABY = 128 * 64;      // bytes per A (hi or lo) buffer
    constexpr int BBY = TN * 64;
    constexpr int STAGE = 2 * ABY + 2 * BBY;
    constexpr int TNW = TN / 4;        // warp N tile
    constexpr int NT = TNW / 8;        // n8 tiles per warp (4 or 2)
    constexpr int NP = NT / 2;         // ldmatrix pairs

    extern __shared__ char smem[];
    const uint32_t s0 = smem_u32(smem);
    const uint32_t sb[2] = {s0, s0 + STAGE};

    const int tid = threadIdx.x;
    const int wid = tid >> 5;
    const int lane = tid & 31;
    const int wm = wid & 1;
    const int wn = wid >> 1;
    const int i0 = blockIdx.y * 128;
    const int j0 = blockIdx.x * TN;

    float acc[4][NT][4];
#pragma unroll
    for (int a = 0; a < 4; a++)
#pragma unroll
        for (int b = 0; b < NT; b++)
#pragma unroll
            for (int c = 0; c < 4; c++) acc[a][b][c] = 0.f;

    auto prefetch = [&](int ch, int s) {
        const uint32_t base = sb[s];
        const int k0 = ch * KC;
#pragma unroll
        for (int it = 0; it < 2; it++) {              // A: 512 chunks hi+lo
            int id = tid + it * 256;
            int row = id >> 2, c = id & 3;
            uint32_t off = row * 64 + (((c ^ (row >> 1)) & 3) << 4);
            const __nv_bfloat16* gh = Ah + (size_t)(i0 + row) * K + k0 + c * 8;
            const __nv_bfloat16* gl = Al + (size_t)(i0 + row) * K + k0 + c * 8;
            CP16(base + off, gh);
            CP16(base + ABY + off, gl);
        }
#pragma unroll
        for (int it = 0; it < (TN * 4) / 256; it++) { // B
            int id = tid + it * 256;
            int row = id >> 2, c = id & 3;
            uint32_t off = row * 64 + (((c ^ (row >> 1)) & 3) << 4);
            const __nv_bfloat16* gh = Bh + (size_t)(j0 + row) * K + k0 + c * 8;
            const __nv_bfloat16* gl = Bl + (size_t)(j0 + row) * K + k0 + c * 8;
            CP16(base + 2 * ABY + off, gh);
            CP16(base + 2 * ABY + BBY + off, gl);
        }
    };

    auto compute = [&](int s) {
        const uint32_t ab = sb[s], alb = ab + ABY;
        const uint32_t bhb = ab + 2 * ABY, blb = bhb + BBY;
#pragma unroll
        for (int ks = 0; ks < 2; ks++) {
            uint32_t BH[NP][4], BL[NP][4];
#pragma unroll
            for (int p = 0; p < NP; p++) {
                int row = wn * TNW + p * 16 + (lane & 15);
                int ch = ks * 2 + (lane >> 4);
                uint32_t off = row * 64 + (((ch ^ (row >> 1)) & 3) << 4);
                LDSM4(BH[p], bhb + off);
                LDSM4(BL[p], blb + off);
            }
#pragma unroll
            for (int mt = 0; mt < 4; mt++) {
                int row = wm * 64 + mt * 16 + (lane & 15);
                int ch = ks * 2 + (lane >> 4);
                uint32_t off = row * 64 + (((ch ^ (row >> 1)) & 3) << 4);
                uint32_t AH[4], AL[4];
                LDSM4(AH, ab + off);
                LDSM4(AL, alb + off);
#pragma unroll
                for (int nt = 0; nt < NT; nt++) {
                    uint32_t b0h = BH[nt >> 1][nt & 1], b1h = BH[nt >> 1][(nt & 1) + 2];
                    uint32_t b0l = BL[nt >> 1][nt & 1], b1l = BL[nt >> 1][(nt & 1) + 2];
                    MMA_BF16(acc[mt][nt], AH, b0h, b1h);
                    MMA_BF16(acc[mt][nt], AH, b0l, b1l);
                    MMA_BF16(acc[mt][nt], AL, b0h, b1h);
                }
            }
        }
    };

    prefetch(0, 0);
    CP_COMMIT();
    for (int ch = 0; ch < NCH; ch++) {
        if (ch + 1 < NCH) {
            prefetch(ch + 1, (ch + 1) & 1);
            CP_COMMIT();
            CP_WAIT(1);
        } else {
            CP_WAIT(0);
        }
        __syncthreads();
        compute(ch & 1);
        __syncthreads();
    }

    // epilogue
#pragma unroll
    for (int mt = 0; mt < 4; mt++) {
        const int gr = i0 + wm * 64 + mt * 16 + (lane >> 2);
#pragma unroll
        for (int nt = 0; nt < NT; nt++) {
            const int gc = j0 + wn * TNW + nt * 8 + (lane & 3) * 2;
            const float b0 = __ldg(bias + gc), b1 = __ldg(bias + gc + 1);
            float v0 = acc[mt][nt][0] + b0, v1 = acc[mt][nt][1] + b1;
            float v2 = acc[mt][nt][2] + b0, v3 = acc[mt][nt][3] + b1;
            if (MODE == 1) {
                v0 = 1.f / (1.f + __expf(-v0)) * (1.f / Nn);
                v1 = 1.f / (1.f + __expf(-v1)) * (1.f / Nn);
                v2 = 1.f / (1.f + __expf(-v2)) * (1.f / Nn);
                v3 = 1.f / (1.f + __expf(-v3)) * (1.f / Nn);
            }
            *(float2*)(Cout + (size_t)gr * J + gc) = make_float2(v0, v1);
            *(float2*)(Cout + (size_t)(gr + 8) * J + gc) = make_float2(v2, v3);
        }
    }
}

// ---------------- batched TN GEMM (z = ct^T @ x), fp32 SIMT ------------------
__global__ __launch_bounds__(256) void gemm_tn(
    const float* __restrict__ A, const float* __restrict__ Bx,
    float* __restrict__ Cm,
    int I, int J, int K, int lda, int ldb, int ldc,
    long sA, long sB, long sC)
{
    A  += (long)blockIdx.z * sA;
    Bx += (long)blockIdx.z * sB;
    Cm += (long)blockIdx.z * sC;

    __shared__ float As[16][64];
    __shared__ float Bs[16][64];
    const int tid = threadIdx.x;
    const int i0 = blockIdx.y * 64;
    const int j0 = blockIdx.x * 64;
    const int tx = tid & 15, ty = tid >> 4;
    const int kr = tid >> 4;
    const int ic = (tid & 15) << 2;

    float acc[4][4];
#pragma unroll
    for (int r = 0; r < 4; r++)
#pragma unroll
        for (int c = 0; c < 4; c++) acc[r][c] = 0.f;

    for (int k0 = 0; k0 < K; k0 += 16) {
        *(float4*)&As[kr][ic] = *(const float4*)(A  + (long)(k0 + kr) * lda + i0 + ic);
        *(float4*)&Bs[kr][ic] = *(const float4*)(Bx + (long)(k0 + kr) * ldb + j0 + ic);
        __syncthreads();
#pragma unroll
        for (int kk = 0; kk < 16; kk++) {
            float av[4], bv[4];
#pragma unroll
            for (int r = 0; r < 4; r++) av[r] = As[kk][ty * 4 + r];
#pragma unroll
            for (int c = 0; c < 4; c++) bv[c] = Bs[kk][tx * 4 + c];
#pragma unroll
            for (int r = 0; r < 4; r++)
#pragma unroll
                for (int c = 0; c < 4; c++) acc[r][c] += av[r] * bv[c];
        }
        __syncthreads();
    }
#pragma unroll
    for (int r = 0; r < 4; r++) {
        const int i = i0 + ty * 4 + r;
#pragma unroll
        for (int c = 0; c < 4; c++)
            Cm[(long)i * ldc + j0 + tx * 4 + c] = acc[r][c];
    }
}

// ---------------- L2 normalize + emit bf16 hi/lo ----------------------------
__global__ __launch_bounds__(256) void l2norm(const float* __restrict__ z,
                                              __nv_bfloat16* __restrict__ zh,
                                              __nv_bfloat16* __restrict__ zl)
{
    const int row = blockIdx.x;
    const float* p = z + (long)row * Cc;
    float s = 0.f;
    for (int c = threadIdx.x; c < Cc; c += 256) { float v = p[c]; s += v * v; }
    __shared__ float red[256];
    red[threadIdx.x] = s;
    __syncthreads();
    for (int st = 128; st > 0; st >>= 1) {
        if (threadIdx.x < st) red[threadIdx.x] += red[threadIdx.x + st];
        __syncthreads();
    }
    const float inv = 1.f / fmaxf(sqrtf(red[0]), 1e-12f);
    for (int c = threadIdx.x * 2; c < Cc; c += 512) {
        uint32_t h, l;
        split2(p[c] * inv, p[c + 1] * inv, h, l);
        *(uint32_t*)&zh[(long)row * Cc + c] = h;
        *(uint32_t*)&zl[(long)row * Cc + c] = l;
    }
}

// ---------------- fused attention (emits bf16 hi/lo o) ----------------------
__global__ __launch_bounds__(128) void attn_kernel(
    const float* __restrict__ q, const float* __restrict__ k,
    const float* __restrict__ v,
    __nv_bfloat16* __restrict__ oh, __nv_bfloat16* __restrict__ ol)
{
    const int bh = blockIdx.x;
    const int b = bh / Hh;
    const int h = bh % Hh;
    const int n = blockIdx.y * 128 + threadIdx.x;

    __shared__ float ks[Mm][Dd];
    __shared__ float vs[Mm][Dd];
    for (int idx = threadIdx.x; idx < Mm * (Dd / 4); idx += 128) {
        const int m = idx >> 4;
        const int d4 = (idx & 15) << 2;
        const long base = ((long)b * Mm + m) * Cc + h * Dd + d4;
        *(float4*)&ks[m][d4] = *(const float4*)&k[base];
        *(float4*)&vs[m][d4] = *(const float4*)&v[base];
    }
    __syncthreads();

    float qd[Dd];
    const float* qp = q + ((long)b * Nn + n) * Cc + h * Dd;
#pragma unroll
    for (int d4 = 0; d4 < Dd; d4 += 4) {
        float4 t = *(const float4*)(qp + d4);
        qd[d4] = t.x; qd[d4 + 1] = t.y; qd[d4 + 2] = t.z; qd[d4 + 3] = t.w;
    }

    float oacc[Dd];
#pragma unroll
    for (int d = 0; d < Dd; d++) oacc[d] = 0.f;
    float mmax = -1e30f, lsum = 0.f;
    const float scale = 0.125f;

    for (int m = 0; m < Mm; m++) {
        float s = 0.f;
#pragma unroll
        for (int d = 0; d < Dd; d++) s += qd[d] * ks[m][d];
        s *= scale;
        const float nm = fmaxf(mmax, s);
        const float corr = __expf(mmax - nm);
        const float pr = __expf(s - nm);
        lsum = lsum * corr + pr;
#pragma unroll
        for (int d = 0; d < Dd; d++) oacc[d] = oacc[d] * corr + pr * vs[m][d];
        mmax = nm;
    }

    const float inv = 1.f / lsum;
    const long ob = ((long)b * Nn + n) * Cc + h * Dd;
#pragma unroll
    for (int d4 = 0; d4 < Dd; d4 += 4) {
        uint32_t h0, l0, h1, l1;
        split2(oacc[d4] * inv, oacc[d4 + 1] * inv, h0, l0);
        split2(oacc[d4 + 2] * inv, oacc[d4 + 3] * inv, h1, l1);
        *(uint2*)&oh[ob + d4] = make_uint2(h0, h1);
        *(uint2*)&ol[ob + d4] = make_uint2(l0, l1);
    }
}

// ---------------------------------------------------------------------------
extern "C" void kernel_launch(void* const* d_in, const int* in_sizes, int n_in,
                              void* d_out, int out_size)
{
    (void)in_sizes; (void)n_in; (void)out_size;
    const float* x  = (const float*)d_in[0];
    const float* Wc = (const float*)d_in[1];
    const float* bc = (const float*)d_in[2];
    const float* Wq = (const float*)d_in[3];
    const float* bq = (const float*)d_in[4];
    const float* Wk = (const float*)d_in[5];
    const float* bk = (const float*)d_in[6];
    const float* Wv = (const float*)d_in[7];
    const float* bv = (const float*)d_in[8];
    const float* Wp = (const float*)d_in[9];
    const float* bp = (const float*)d_in[10];
    float* out = (float*)d_out;

    float *ct, *z, *q, *k, *v;
    __nv_bfloat16 *xh, *xl, *oh, *ol, *zh, *zl, *wh, *wl;
    cudaGetSymbolAddress((void**)&ct, g_ct);
    cudaGetSymbolAddress((void**)&z,  g_z);
    cudaGetSymbolAddress((void**)&q,  g_q);
    cudaGetSymbolAddress((void**)&k,  g_k);
    cudaGetSymbolAddress((void**)&v,  g_v);
    cudaGetSymbolAddress((void**)&xh, g_xh);
    cudaGetSymbolAddress((void**)&xl, g_xl);
    cudaGetSymbolAddress((void**)&oh, g_oh);
    cudaGetSymbolAddress((void**)&ol, g_ol);
    cudaGetSymbolAddress((void**)&zh, g_zh);
    cudaGetSymbolAddress((void**)&zl, g_zl);
    cudaGetSymbolAddress((void**)&wh, g_wh);
    cudaGetSymbolAddress((void**)&wl, g_wl);

    // stage = 2*A(8KB) + 2*B ; double-buffered
    constexpr int SMEM128 = 2 * (2 * 128 * 64 + 2 * 128 * 64);  // 65536
    constexpr int SMEM64  = 2 * (2 * 128 * 64 + 2 * 64 * 64);   // 49152
    cudaFuncSetAttribute(gemm_tc<128, 0>,
        cudaFuncAttributeMaxDynamicSharedMemorySize, SMEM128);
    cudaFuncSetAttribute(gemm_tc<64, 1>,
        cudaFuncAttributeMaxDynamicSharedMemorySize, SMEM64);

    const int IN = Bb * Nn;   // 32768
    const int IM = Bb * Mm;   // 2048

    // 0. split-convert x and all weights to bf16 hi/lo
    {
        int n4 = IN * Cc / 4;
        cvt_hl<<<(n4 + 255) / 256, 256>>>((const float4*)x, (uint2*)xh, (uint2*)xl, n4);
        n4 = Mm * Cc / 4;
        cvt_hl<<<(n4 + 255) / 256, 256>>>((const float4*)Wc,
            (uint2*)(wh + W_OFF_C), (uint2*)(wl + W_OFF_C), n4);
        n4 = Cc * Cc / 4;
        cvt_hl<<<(n4 + 255) / 256, 256>>>((const float4*)Wq,
            (uint2*)(wh + W_OFF_Q), (uint2*)(wl + W_OFF_Q), n4);
        cvt_hl<<<(n4 + 255) / 256, 256>>>((const float4*)Wk,
            (uint2*)(wh + W_OFF_K), (uint2*)(wl + W_OFF_K), n4);
        cvt_hl<<<(n4 + 255) / 256, 256>>>((const float4*)Wv,
            (uint2*)(wh + W_OFF_V), (uint2*)(wl + W_OFF_V), n4);
        cvt_hl<<<(n4 + 255) / 256, 256>>>((const float4*)Wp,
            (uint2*)(wh + W_OFF_P), (uint2*)(wl + W_OFF_P), n4);
    }

    // 1. cluster logits: ct = sigmoid(x @ Wc^T + bc)/N   (32768 x 64)
    gemm_tc<64, 1><<<dim3(1, IN / 128), 256, SMEM64>>>(
        xh, xl, wh + W_OFF_C, wl + W_OFF_C, bc, ct, Mm);

    // 2. z[b] = ct[b]^T @ x[b]
    gemm_tn<<<dim3(Cc / 64, Mm / 64, Bb), 256>>>(
        ct, x, z, Mm, Cc, Nn, Mm, Cc, Cc,
        (long)Nn * Mm, (long)Nn * Cc, (long)Mm * Cc);

    // 3. L2 normalize z rows -> bf16 hi/lo
    l2norm<<<IM, 256>>>(z, zh, zl);

    // 4. Q = x @ Wq^T + bq
    gemm_tc<128, 0><<<dim3(Cc / 128, IN / 128), 256, SMEM128>>>(
        xh, xl, wh + W_OFF_Q, wl + W_OFF_Q, bq, q, Cc);

    // 5/6. K,V = z @ W^T + b
    gemm_tc<128, 0><<<dim3(Cc / 128, IM / 128), 256, SMEM128>>>(
        zh, zl, wh + W_OFF_K, wl + W_OFF_K, bk, k, Cc);
    gemm_tc<128, 0><<<dim3(Cc / 128, IM / 128), 256, SMEM128>>>(
        zh, zl, wh + W_OFF_V, wl + W_OFF_V, bv, v, Cc);

    // 7. fused attention -> o (bf16 hi/lo)
    attn_kernel<<<dim3(Bb * Hh, Nn / 128), 128>>>(q, k, v, oh, ol);

    // 8. out = o @ Wp^T + bp
    gemm_tc<128, 0><<<dim3(Cc / 128, IN / 128), 256, SMEM128>>>(
        oh, ol, wh + W_OFF_P, wl + W_OFF_P, bp, out, Cc);
}

// round 7
// speedup vs baseline: 2.9236x; 1.1714x over previous
#include <cuda_runtime.h>
#include <cuda_fp16.h>
#include <math.h>
#include <stdint.h>

#define Bb 32
#define Nn 1024
#define Cc 768
#define Mm 64
#define Hh 12
#define Dd 64

// ---------------- scratch (__device__ globals per allocation contract) ------
__device__ float g_ct[Bb * Nn * Mm];
__device__ float g_z [Bb * Mm * Cc];
__device__ float g_q [Bb * Nn * Cc];
__device__ float g_k [Bb * Mm * Cc];
__device__ float g_v [Bb * Mm * Cc];

__device__ __half g_xh[Bb * Nn * Cc];     // activations: hi only (fp16)
__device__ __half g_oh[Bb * Nn * Cc];
__device__ __half g_zh[Bb * Mm * Cc];
#define W_OFF_C 0
#define W_OFF_Q (Mm * Cc)
#define W_OFF_K (W_OFF_Q + Cc * Cc)
#define W_OFF_V (W_OFF_K + Cc * Cc)
#define W_OFF_P (W_OFF_V + Cc * Cc)
#define W_TOTAL (W_OFF_P + Cc * Cc)
__device__ __half g_wh[W_TOTAL], g_wl[W_TOTAL];   // weights: fp16 hi + lo

// ---------------- helpers ---------------------------------------------------
__device__ __forceinline__ uint32_t smem_u32(const void* p) {
    uint32_t a;
    asm("{ .reg .u64 t; cvta.to.shared.u64 t, %1; cvt.u32.u64 %0, t; }"
        : "=r"(a) : "l"(p));
    return a;
}
#define CP16(saddr, gaddr) \
    asm volatile("cp.async.cg.shared.global [%0], [%1], 16;" \
                 :: "r"(saddr), "l"(gaddr))
#define CP_COMMIT() asm volatile("cp.async.commit_group;")
#define CP_WAIT(n)  asm volatile("cp.async.wait_group %0;" :: "n"(n))

#define LDSM4(r, a) \
    asm volatile("ldmatrix.sync.aligned.m8n8.x4.shared.b16 {%0,%1,%2,%3}, [%4];" \
        : "=r"((r)[0]), "=r"((r)[1]), "=r"((r)[2]), "=r"((r)[3]) : "r"(a))

#define MMA_F16(c, a, b0, b1) \
    asm volatile("mma.sync.aligned.m16n8k16.row.col.f32.f16.f16.f32 " \
        "{%0,%1,%2,%3},{%4,%5,%6,%7},{%8,%9},{%0,%1,%2,%3};" \
        : "+f"((c)[0]), "+f"((c)[1]), "+f"((c)[2]), "+f"((c)[3]) \
        : "r"((a)[0]), "r"((a)[1]), "r"((a)[2]), "r"((a)[3]), "r"(b0), "r"(b1))

__device__ __forceinline__ void wsplit2(float a, float b, uint32_t& hi, uint32_t& lo) {
    __half ha = __float2half_rn(a), hb = __float2half_rn(b);
    float ra = a - __half2float(ha);
    float rb = b - __half2float(hb);
    __half2 H, L;
    H.x = ha; H.y = hb;
    L.x = __float2half_rn(ra); L.y = __float2half_rn(rb);
    hi = *(uint32_t*)&H; lo = *(uint32_t*)&L;
}

// ---------------- converters -------------------------------------------------
__global__ __launch_bounds__(256) void cvt_h(const float4* __restrict__ in,
                                             uint2* __restrict__ hi, int n4) {
    int i = blockIdx.x * 256 + threadIdx.x;
    if (i >= n4) return;
    float4 a = in[i];
    __half2 h0 = __floats2half2_rn(a.x, a.y);
    __half2 h1 = __floats2half2_rn(a.z, a.w);
    hi[i] = make_uint2(*(uint32_t*)&h0, *(uint32_t*)&h1);
}
__global__ __launch_bounds__(256) void cvt_hl(const float4* __restrict__ in,
                                              uint2* __restrict__ hi,
                                              uint2* __restrict__ lo, int n4) {
    int i = blockIdx.x * 256 + threadIdx.x;
    if (i >= n4) return;
    float4 a = in[i];
    uint32_t h0, l0, h1, l1;
    wsplit2(a.x, a.y, h0, l0);
    wsplit2(a.z, a.w, h1, l1);
    hi[i] = make_uint2(h0, h1);
    lo[i] = make_uint2(l0, l1);
}

// ---------------- split-fp16 GEMM NT via mma.sync ---------------------------
// C(I,J) = A(I,768)·B(J,768)^T + bias [, sigmoid/N].
// A: fp16 hi only. B: fp16 hi + lo. 2 MMAs per k-step: ah·bh + ah·bl = ah·b.
// Block 128 x TN, 8 warps (2M x 4N); warp tile 64 x TN/4; KC=32; 2-stage cp.async.
template <int TN, int MODE>
__global__ __launch_bounds__(256) void gemm_tc(
    const __half* __restrict__ Ah,
    const __half* __restrict__ Bh, const __half* __restrict__ Bl,
    const float* __restrict__ bias, float* __restrict__ Cout, int J)
{
    constexpr int K = Cc;
    constexpr int KC = 32;
    constexpr int NCH = K / KC;        // 24
    constexpr int ABY = 128 * 64;      // 8 KB  (128 rows x 64B)
    constexpr int BBY = TN * 64;
    constexpr int STAGE = ABY + 2 * BBY;
    constexpr int TNW = TN / 4;
    constexpr int NT = TNW / 8;
    constexpr int NP = NT / 2;

    extern __shared__ char smem[];
    const uint32_t s0 = smem_u32(smem);
    const uint32_t sb[2] = {s0, s0 + STAGE};

    const int tid = threadIdx.x;
    const int wid = tid >> 5;
    const int lane = tid & 31;
    const int wm = wid & 1;
    const int wn = wid >> 1;
    const int i0 = blockIdx.y * 128;
    const int j0 = blockIdx.x * TN;

    float acc[4][NT][4];
#pragma unroll
    for (int a = 0; a < 4; a++)
#pragma unroll
        for (int b = 0; b < NT; b++)
#pragma unroll
            for (int c = 0; c < 4; c++) acc[a][b][c] = 0.f;

    auto prefetch = [&](int ch, int s) {
        const uint32_t base = sb[s];
        const int k0 = ch * KC;
#pragma unroll
        for (int it = 0; it < 2; it++) {              // A hi: 128 rows x 4 chunks
            int id = tid + it * 256;
            int row = id >> 2, c = id & 3;
            uint32_t off = row * 64 + (((c ^ (row >> 1)) & 3) << 4);
            CP16(base + off, Ah + (size_t)(i0 + row) * K + k0 + c * 8);
        }
#pragma unroll
        for (int it = 0; it < (TN * 4) / 256; it++) { // B hi + lo
            int id = tid + it * 256;
            int row = id >> 2, c = id & 3;
            uint32_t off = row * 64 + (((c ^ (row >> 1)) & 3) << 4);
            CP16(base + ABY + off,       Bh + (size_t)(j0 + row) * K + k0 + c * 8);
            CP16(base + ABY + BBY + off, Bl + (size_t)(j0 + row) * K + k0 + c * 8);
        }
    };

    auto compute = [&](int s) {
        const uint32_t ab = sb[s];
        const uint32_t bhb = ab + ABY, blb = bhb + BBY;
#pragma unroll
        for (int ks = 0; ks < 2; ks++) {
            uint32_t BH[NP][4], BL[NP][4];
#pragma unroll
            for (int p = 0; p < NP; p++) {
                int row = wn * TNW + p * 16 + (lane & 15);
                int ch = ks * 2 + (lane >> 4);
                uint32_t off = row * 64 + (((ch ^ (row >> 1)) & 3) << 4);
                LDSM4(BH[p], bhb + off);
                LDSM4(BL[p], blb + off);
            }
#pragma unroll
            for (int mt = 0; mt < 4; mt++) {
                int row = wm * 64 + mt * 16 + (lane & 15);
                int ch = ks * 2 + (lane >> 4);
                uint32_t off = row * 64 + (((ch ^ (row >> 1)) & 3) << 4);
                uint32_t AH[4];
                LDSM4(AH, ab + off);
#pragma unroll
                for (int nt = 0; nt < NT; nt++) {
                    uint32_t b0h = BH[nt >> 1][nt & 1], b1h = BH[nt >> 1][(nt & 1) + 2];
                    uint32_t b0l = BL[nt >> 1][nt & 1], b1l = BL[nt >> 1][(nt & 1) + 2];
                    MMA_F16(acc[mt][nt], AH, b0h, b1h);
                    MMA_F16(acc[mt][nt], AH, b0l, b1l);
                }
            }
        }
    };

    prefetch(0, 0);
    CP_COMMIT();
    for (int ch = 0; ch < NCH; ch++) {
        if (ch + 1 < NCH) {
            prefetch(ch + 1, (ch + 1) & 1);
            CP_COMMIT();
            CP_WAIT(1);
        } else {
            CP_WAIT(0);
        }
        __syncthreads();
        compute(ch & 1);
        __syncthreads();
    }

#pragma unroll
    for (int mt = 0; mt < 4; mt++) {
        const int gr = i0 + wm * 64 + mt * 16 + (lane >> 2);
#pragma unroll
        for (int nt = 0; nt < NT; nt++) {
            const int gc = j0 + wn * TNW + nt * 8 + (lane & 3) * 2;
            const float b0 = __ldg(bias + gc), b1 = __ldg(bias + gc + 1);
            float v0 = acc[mt][nt][0] + b0, v1 = acc[mt][nt][1] + b1;
            float v2 = acc[mt][nt][2] + b0, v3 = acc[mt][nt][3] + b1;
            if (MODE == 1) {
                v0 = 1.f / (1.f + __expf(-v0)) * (1.f / Nn);
                v1 = 1.f / (1.f + __expf(-v1)) * (1.f / Nn);
                v2 = 1.f / (1.f + __expf(-v2)) * (1.f / Nn);
                v3 = 1.f / (1.f + __expf(-v3)) * (1.f / Nn);
            }
            *(float2*)(Cout + (size_t)gr * J + gc) = make_float2(v0, v1);
            *(float2*)(Cout + (size_t)(gr + 8) * J + gc) = make_float2(v2, v3);
        }
    }
}

// ---------------- batched TN GEMM (z = ct^T @ x), fp32 SIMT ------------------
__global__ __launch_bounds__(256) void gemm_tn(
    const float* __restrict__ A, const float* __restrict__ Bx,
    float* __restrict__ Cm,
    int I, int J, int K, int lda, int ldb, int ldc,
    long sA, long sB, long sC)
{
    A  += (long)blockIdx.z * sA;
    Bx += (long)blockIdx.z * sB;
    Cm += (long)blockIdx.z * sC;

    __shared__ float As[16][64];
    __shared__ float Bs[16][64];
    const int tid = threadIdx.x;
    const int i0 = blockIdx.y * 64;
    const int j0 = blockIdx.x * 64;
    const int tx = tid & 15, ty = tid >> 4;
    const int kr = tid >> 4;
    const int ic = (tid & 15) << 2;

    float acc[4][4];
#pragma unroll
    for (int r = 0; r < 4; r++)
#pragma unroll
        for (int c = 0; c < 4; c++) acc[r][c] = 0.f;

    for (int k0 = 0; k0 < K; k0 += 16) {
        *(float4*)&As[kr][ic] = *(const float4*)(A  + (long)(k0 + kr) * lda + i0 + ic);
        *(float4*)&Bs[kr][ic] = *(const float4*)(Bx + (long)(k0 + kr) * ldb + j0 + ic);
        __syncthreads();
#pragma unroll
        for (int kk = 0; kk < 16; kk++) {
            float av[4], bv[4];
#pragma unroll
            for (int r = 0; r < 4; r++) av[r] = As[kk][ty * 4 + r];
#pragma unroll
            for (int c = 0; c < 4; c++) bv[c] = Bs[kk][tx * 4 + c];
#pragma unroll
            for (int r = 0; r < 4; r++)
#pragma unroll
                for (int c = 0; c < 4; c++) acc[r][c] += av[r] * bv[c];
        }
        __syncthreads();
    }
#pragma unroll
    for (int r = 0; r < 4; r++) {
        const int i = i0 + ty * 4 + r;
#pragma unroll
        for (int c = 0; c < 4; c++)
            Cm[(long)i * ldc + j0 + tx * 4 + c] = acc[r][c];
    }
}

// ---------------- L2 normalize + emit fp16 ----------------------------------
__global__ __launch_bounds__(256) void l2norm(const float* __restrict__ z,
                                              __half* __restrict__ zh)
{
    const int row = blockIdx.x;
    const float* p = z + (long)row * Cc;
    float s = 0.f;
    for (int c = threadIdx.x; c < Cc; c += 256) { float v = p[c]; s += v * v; }
    __shared__ float red[256];
    red[threadIdx.x] = s;
    __syncthreads();
    for (int st = 128; st > 0; st >>= 1) {
        if (threadIdx.x < st) red[threadIdx.x] += red[threadIdx.x + st];
        __syncthreads();
    }
    const float inv = 1.f / fmaxf(sqrtf(red[0]), 1e-12f);
    for (int c = threadIdx.x * 2; c < Cc; c += 512) {
        __half2 h = __floats2half2_rn(p[c] * inv, p[c + 1] * inv);
        *(uint32_t*)&zh[(long)row * Cc + c] = *(uint32_t*)&h;
    }
}

// ---------------- fused attention (chunked two-pass softmax, fp16 out) ------
__global__ __launch_bounds__(128) void attn_kernel(
    const float* __restrict__ q, const float* __restrict__ k,
    const float* __restrict__ v, __half* __restrict__ oh)
{
    const int bh = blockIdx.x;
    const int b = bh / Hh;
    const int h = bh % Hh;
    const int n = blockIdx.y * 128 + threadIdx.x;

    __shared__ float ks[Mm][Dd];
    __shared__ float vs[Mm][Dd];
    for (int idx = threadIdx.x; idx < Mm * (Dd / 4); idx += 128) {
        const int m = idx >> 4;
        const int d4 = (idx & 15) << 2;
        const long base = ((long)b * Mm + m) * Cc + h * Dd + d4;
        *(float4*)&ks[m][d4] = *(const float4*)&k[base];
        *(float4*)&vs[m][d4] = *(const float4*)&v[base];
    }
    __syncthreads();

    float qd[Dd];
    const float* qp = q + ((long)b * Nn + n) * Cc + h * Dd;
#pragma unroll
    for (int d4 = 0; d4 < Dd; d4 += 4) {
        float4 t = *(const float4*)(qp + d4);
        qd[d4] = t.x; qd[d4 + 1] = t.y; qd[d4 + 2] = t.z; qd[d4 + 3] = t.w;
    }

    float oacc[Dd];
#pragma unroll
    for (int d = 0; d < Dd; d++) oacc[d] = 0.f;
    float mmax = -1e30f, lsum = 0.f;
    const float scale = 0.125f;

    // chunks of 16 keys: score once, one exp per score, one rescale per chunk
#pragma unroll
    for (int c0 = 0; c0 < Mm; c0 += 16) {
        float s[16];
#pragma unroll
        for (int i = 0; i < 16; i++) {
            float acc = 0.f;
#pragma unroll
            for (int d = 0; d < Dd; d++) acc += qd[d] * ks[c0 + i][d];
            s[i] = acc * scale;
        }
        float cmax = s[0];
#pragma unroll
        for (int i = 1; i < 16; i++) cmax = fmaxf(cmax, s[i]);
        const float nm = fmaxf(mmax, cmax);
        const float corr = __expf(mmax - nm);
        lsum *= corr;
#pragma unroll
        for (int d = 0; d < Dd; d++) oacc[d] *= corr;
#pragma unroll
        for (int i = 0; i < 16; i++) {
            const float p = __expf(s[i] - nm);
            lsum += p;
#pragma unroll
            for (int d = 0; d < Dd; d++) oacc[d] += p * vs[c0 + i][d];
        }
        mmax = nm;
    }

    const float inv = 1.f / lsum;
    const long ob = ((long)b * Nn + n) * Cc + h * Dd;
#pragma unroll
    for (int d4 = 0; d4 < Dd; d4 += 4) {
        __half2 h0 = __floats2half2_rn(oacc[d4] * inv, oacc[d4 + 1] * inv);
        __half2 h1 = __floats2half2_rn(oacc[d4 + 2] * inv, oacc[d4 + 3] * inv);
        *(uint2*)&oh[ob + d4] = make_uint2(*(uint32_t*)&h0, *(uint32_t*)&h1);
    }
}

// ---------------------------------------------------------------------------
extern "C" void kernel_launch(void* const* d_in, const int* in_sizes, int n_in,
                              void* d_out, int out_size)
{
    (void)in_sizes; (void)n_in; (void)out_size;
    const float* x  = (const float*)d_in[0];
    const float* Wc = (const float*)d_in[1];
    const float* bc = (const float*)d_in[2];
    const float* Wq = (const float*)d_in[3];
    const float* bq = (const float*)d_in[4];
    const float* Wk = (const float*)d_in[5];
    const float* bk = (const float*)d_in[6];
    const float* Wv = (const float*)d_in[7];
    const float* bv = (const float*)d_in[8];
    const float* Wp = (const float*)d_in[9];
    const float* bp = (const float*)d_in[10];
    float* out = (float*)d_out;

    float *ct, *z, *q, *k, *v;
    __half *xh, *oh, *zh, *wh, *wl;
    cudaGetSymbolAddress((void**)&ct, g_ct);
    cudaGetSymbolAddress((void**)&z,  g_z);
    cudaGetSymbolAddress((void**)&q,  g_q);
    cudaGetSymbolAddress((void**)&k,  g_k);
    cudaGetSymbolAddress((void**)&v,  g_v);
    cudaGetSymbolAddress((void**)&xh, g_xh);
    cudaGetSymbolAddress((void**)&oh, g_oh);
    cudaGetSymbolAddress((void**)&zh, g_zh);
    cudaGetSymbolAddress((void**)&wh, g_wh);
    cudaGetSymbolAddress((void**)&wl, g_wl);

    // stage = A(8KB) + 2*B ; double-buffered
    constexpr int SMEM128 = 2 * (128 * 64 + 2 * 128 * 64);  // 49152
    constexpr int SMEM64  = 2 * (128 * 64 + 2 * 64 * 64);   // 32768
    cudaFuncSetAttribute(gemm_tc<128, 0>,
        cudaFuncAttributeMaxDynamicSharedMemorySize, SMEM128);
    cudaFuncSetAttribute(gemm_tc<64, 1>,
        cudaFuncAttributeMaxDynamicSharedMemorySize, SMEM64);

    const int IN = Bb * Nn;   // 32768
    const int IM = Bb * Mm;   // 2048

    // 0. convert activations (hi) and weights (hi+lo) to fp16
    {
        int n4 = IN * Cc / 4;
        cvt_h<<<(n4 + 255) / 256, 256>>>((const float4*)x, (uint2*)xh, n4);
        n4 = Mm * Cc / 4;
        cvt_hl<<<(n4 + 255) / 256, 256>>>((const float4*)Wc,
            (uint2*)(wh + W_OFF_C), (uint2*)(wl + W_OFF_C), n4);
        n4 = Cc * Cc / 4;
        cvt_hl<<<(n4 + 255) / 256, 256>>>((const float4*)Wq,
            (uint2*)(wh + W_OFF_Q), (uint2*)(wl + W_OFF_Q), n4);
        cvt_hl<<<(n4 + 255) / 256, 256>>>((const float4*)Wk,
            (uint2*)(wh + W_OFF_K), (uint2*)(wl + W_OFF_K), n4);
        cvt_hl<<<(n4 + 255) / 256, 256>>>((const float4*)Wv,
            (uint2*)(wh + W_OFF_V), (uint2*)(wl + W_OFF_V), n4);
        cvt_hl<<<(n4 + 255) / 256, 256>>>((const float4*)Wp,
            (uint2*)(wh + W_OFF_P), (uint2*)(wl + W_OFF_P), n4);
    }

    // 1. cluster logits: ct = sigmoid(x @ Wc^T + bc)/N   (32768 x 64)
    gemm_tc<64, 1><<<dim3(1, IN / 128), 256, SMEM64>>>(
        xh, wh + W_OFF_C, wl + W_OFF_C, bc, ct, Mm);

    // 2. z[b] = ct[b]^T @ x[b]
    gemm_tn<<<dim3(Cc / 64, Mm / 64, Bb), 256>>>(
        ct, x, z, Mm, Cc, Nn, Mm, Cc, Cc,
        (long)Nn * Mm, (long)Nn * Cc, (long)Mm * Cc);

    // 3. L2 normalize z rows -> fp16
    l2norm<<<IM, 256>>>(z, zh);

    // 4. Q = x @ Wq^T + bq
    gemm_tc<128, 0><<<dim3(Cc / 128, IN / 128), 256, SMEM128>>>(
        xh, wh + W_OFF_Q, wl + W_OFF_Q, bq, q, Cc);

    // 5/6. K,V = z @ W^T + b
    gemm_tc<128, 0><<<dim3(Cc / 128, IM / 128), 256, SMEM128>>>(
        zh, wh + W_OFF_K, wl + W_OFF_K, bk, k, Cc);
    gemm_tc<128, 0><<<dim3(Cc / 128, IM / 128), 256, SMEM128>>>(
        zh, wh + W_OFF_V, wl + W_OFF_V, bv, v, Cc);

    // 7. fused attention -> o (fp16)
    attn_kernel<<<dim3(Bb * Hh, Nn / 128), 128>>>(q, k, v, oh);

    // 8. out = o @ Wp^T + bp
    gemm_tc<128, 0><<<dim3(Cc / 128, IN / 128), 256, SMEM128>>>(
        oh, wh + W_OFF_P, wl + W_OFF_P, bp, out, Cc);
}

// round 11
// speedup vs baseline: 3.6228x; 1.2392x over previous
#include <cuda_runtime.h>
#include <cuda_fp16.h>
#include <math.h>
#include <stdint.h>

#define Bb 32
#define Nn 1024
#define Cc 768
#define Mm 64
#define Hh 12
#define Dd 64

// ---------------- scratch (__device__ globals per allocation contract) ------
__device__ float g_ct[Bb * Nn * Mm];
__device__ float g_z [Bb * Mm * Cc];
__device__ float g_q [Bb * Nn * Cc];
__device__ float g_kv[Bb * Mm * 2 * Cc];   // fused K|V rows: (B*M, 1536)
__device__ float g_bkv[2 * Cc];

__device__ __half g_xh[Bb * Nn * Cc];      // activations: fp16 hi only
__device__ __half g_oh[Bb * Nn * Cc];
__device__ __half g_zh[Bb * Mm * Cc];
#define W_OFF_C 0
#define W_OFF_Q (Mm * Cc)
#define W_OFF_K (W_OFF_Q + Cc * Cc)
#define W_OFF_V (W_OFF_K + Cc * Cc)
#define W_OFF_P (W_OFF_V + Cc * Cc)
#define W_TOTAL (W_OFF_P + Cc * Cc)
__device__ __half g_wh[W_TOTAL];
__device__ __half g_wcl[Mm * Cc];          // lo part only for Wc (2-term cluster)

// ---------------- helpers ---------------------------------------------------
__device__ __forceinline__ uint32_t smem_u32(const void* p) {
    uint32_t a;
    asm("{ .reg .u64 t; cvta.to.shared.u64 t, %1; cvt.u32.u64 %0, t; }"
        : "=r"(a) : "l"(p));
    return a;
}
#define CP16(saddr, gaddr) \
    asm volatile("cp.async.cg.shared.global [%0], [%1], 16;" \
                 :: "r"(saddr), "l"(gaddr))
#define CP_COMMIT() asm volatile("cp.async.commit_group;")
#define CP_WAIT(n)  asm volatile("cp.async.wait_group %0;" :: "n"(n))

#define LDSM4(r, a) \
    asm volatile("ldmatrix.sync.aligned.m8n8.x4.shared.b16 {%0,%1,%2,%3}, [%4];" \
        : "=r"((r)[0]), "=r"((r)[1]), "=r"((r)[2]), "=r"((r)[3]) : "r"(a))

#define MMA_F16(c, a, b0, b1) \
    asm volatile("mma.sync.aligned.m16n8k16.row.col.f32.f16.f16.f32 " \
        "{%0,%1,%2,%3},{%4,%5,%6,%7},{%8,%9},{%0,%1,%2,%3};" \
        : "+f"((c)[0]), "+f"((c)[1]), "+f"((c)[2]), "+f"((c)[3]) \
        : "r"((a)[0]), "r"((a)[1]), "r"((a)[2]), "r"((a)[3]), "r"(b0), "r"(b1))

__device__ __forceinline__ void wsplit2(float a, float b, uint32_t& hi, uint32_t& lo) {
    __half ha = __float2half_rn(a), hb = __float2half_rn(b);
    float ra = a - __half2float(ha);
    float rb = b - __half2float(hb);
    __half2 H, L;
    H.x = ha; H.y = hb;
    L.x = __float2half_rn(ra); L.y = __float2half_rn(rb);
    hi = *(uint32_t*)&H; lo = *(uint32_t*)&L;
}

// ---------------- converters -------------------------------------------------
__global__ __launch_bounds__(256) void cvt_h(const float4* __restrict__ in,
                                             uint2* __restrict__ hi, int n4) {
    int i = blockIdx.x * 256 + threadIdx.x;
    if (i >= n4) return;
    float4 a = in[i];
    __half2 h0 = __floats2half2_rn(a.x, a.y);
    __half2 h1 = __floats2half2_rn(a.z, a.w);
    hi[i] = make_uint2(*(uint32_t*)&h0, *(uint32_t*)&h1);
}
__global__ __launch_bounds__(256) void cvt_hl(const float4* __restrict__ in,
                                              uint2* __restrict__ hi,
                                              uint2* __restrict__ lo, int n4) {
    int i = blockIdx.x * 256 + threadIdx.x;
    if (i >= n4) return;
    float4 a = in[i];
    uint32_t h0, l0, h1, l1;
    wsplit2(a.x, a.y, h0, l0);
    wsplit2(a.z, a.w, h1, l1);
    hi[i] = make_uint2(h0, h1);
    lo[i] = make_uint2(l0, l1);
}

// ---------------- fp16 GEMM NT via mma.sync ---------------------------------
// C(I,J) = A(I,768)·B(J,768)^T + bias [, sigmoid/N].
// TWO=true: B = hi + lo (2 MMAs/k-step); TWO=false: B = hi (1 MMA/k-step).
// Block 128 x TN, 8 warps (2M x 4N); warp tile 64 x TN/4; KC=32; 2-stage cp.async.
template <int TN, int MODE, bool TWO>
__global__ __launch_bounds__(256) void gemm_tc(
    const __half* __restrict__ Ah,
    const __half* __restrict__ Bh, const __half* __restrict__ Bl,
    const float* __restrict__ bias, float* __restrict__ Cout, int J)
{
    constexpr int K = Cc;
    constexpr int KC = 32;
    constexpr int NCH = K / KC;        // 24
    constexpr int ABY = 128 * 64;      // 8 KB
    constexpr int BBY = TN * 64;
    constexpr int STAGE = ABY + (TWO ? 2 : 1) * BBY;
    constexpr int TNW = TN / 4;
    constexpr int NT = TNW / 8;
    constexpr int NP = NT / 2;

    extern __shared__ char smem[];
    const uint32_t s0 = smem_u32(smem);
    const uint32_t sb[2] = {s0, s0 + STAGE};

    const int tid = threadIdx.x;
    const int wid = tid >> 5;
    const int lane = tid & 31;
    const int wm = wid & 1;
    const int wn = wid >> 1;
    const int i0 = blockIdx.y * 128;
    const int j0 = blockIdx.x * TN;

    float acc[4][NT][4];
#pragma unroll
    for (int a = 0; a < 4; a++)
#pragma unroll
        for (int b = 0; b < NT; b++)
#pragma unroll
            for (int c = 0; c < 4; c++) acc[a][b][c] = 0.f;

    auto prefetch = [&](int ch, int s) {
        const uint32_t base = sb[s];
        const int k0 = ch * KC;
#pragma unroll
        for (int it = 0; it < 2; it++) {              // A hi
            int id = tid + it * 256;
            int row = id >> 2, c = id & 3;
            uint32_t off = row * 64 + (((c ^ (row >> 1)) & 3) << 4);
            CP16(base + off, Ah + (size_t)(i0 + row) * K + k0 + c * 8);
        }
#pragma unroll
        for (int it = 0; it < (TN * 4) / 256; it++) { // B hi (+ lo)
            int id = tid + it * 256;
            int row = id >> 2, c = id & 3;
            uint32_t off = row * 64 + (((c ^ (row >> 1)) & 3) << 4);
            CP16(base + ABY + off, Bh + (size_t)(j0 + row) * K + k0 + c * 8);
            if constexpr (TWO)
                CP16(base + ABY + BBY + off,
                     Bl + (size_t)(j0 + row) * K + k0 + c * 8);
        }
    };

    auto compute = [&](int s) {
        const uint32_t ab = sb[s];
        const uint32_t bhb = ab + ABY, blb = bhb + BBY;
#pragma unroll
        for (int ks = 0; ks < 2; ks++) {
            uint32_t BH[NP][4], BL[NP][4];
#pragma unroll
            for (int p = 0; p < NP; p++) {
                int row = wn * TNW + p * 16 + (lane & 15);
                int ch = ks * 2 + (lane >> 4);
                uint32_t off = row * 64 + (((ch ^ (row >> 1)) & 3) << 4);
                LDSM4(BH[p], bhb + off);
                if constexpr (TWO) LDSM4(BL[p], blb + off);
            }
#pragma unroll
            for (int mt = 0; mt < 4; mt++) {
                int row = wm * 64 + mt * 16 + (lane & 15);
                int ch = ks * 2 + (lane >> 4);
                uint32_t off = row * 64 + (((ch ^ (row >> 1)) & 3) << 4);
                uint32_t AH[4];
                LDSM4(AH, ab + off);
#pragma unroll
                for (int nt = 0; nt < NT; nt++) {
                    uint32_t b0h = BH[nt >> 1][nt & 1], b1h = BH[nt >> 1][(nt & 1) + 2];
                    MMA_F16(acc[mt][nt], AH, b0h, b1h);
                    if constexpr (TWO) {
                        uint32_t b0l = BL[nt >> 1][nt & 1];
                        uint32_t b1l = BL[nt >> 1][(nt & 1) + 2];
                        MMA_F16(acc[mt][nt], AH, b0l, b1l);
                    }
                }
            }
        }
    };

    prefetch(0, 0);
    CP_COMMIT();
    for (int ch = 0; ch < NCH; ch++) {
        if (ch + 1 < NCH) {
            prefetch(ch + 1, (ch + 1) & 1);
            CP_COMMIT();
            CP_WAIT(1);
        } else {
            CP_WAIT(0);
        }
        __syncthreads();
        compute(ch & 1);
        __syncthreads();
    }

#pragma unroll
    for (int mt = 0; mt < 4; mt++) {
        const int gr = i0 + wm * 64 + mt * 16 + (lane >> 2);
#pragma unroll
        for (int nt = 0; nt < NT; nt++) {
            const int gc = j0 + wn * TNW + nt * 8 + (lane & 3) * 2;
            const float b0 = __ldg(bias + gc), b1 = __ldg(bias + gc + 1);
            float v0 = acc[mt][nt][0] + b0, v1 = acc[mt][nt][1] + b1;
            float v2 = acc[mt][nt][2] + b0, v3 = acc[mt][nt][3] + b1;
            if (MODE == 1) {
                v0 = 1.f / (1.f + __expf(-v0)) * (1.f / Nn);
                v1 = 1.f / (1.f + __expf(-v1)) * (1.f / Nn);
                v2 = 1.f / (1.f + __expf(-v2)) * (1.f / Nn);
                v3 = 1.f / (1.f + __expf(-v3)) * (1.f / Nn);
            }
            *(float2*)(Cout + (size_t)gr * J + gc) = make_float2(v0, v1);
            *(float2*)(Cout + (size_t)(gr + 8) * J + gc) = make_float2(v2, v3);
        }
    }
}

// ---------------- batched TN GEMM (z = ct^T @ x), fp32 SIMT ------------------
__global__ __launch_bounds__(256) void gemm_tn(
    const float* __restrict__ A, const float* __restrict__ Bx,
    float* __restrict__ Cm,
    int I, int J, int K, int lda, int ldb, int ldc,
    long sA, long sB, long sC)
{
    A  += (long)blockIdx.z * sA;
    Bx += (long)blockIdx.z * sB;
    Cm += (long)blockIdx.z * sC;

    __shared__ float As[16][64];
    __shared__ float Bs[16][64];
    const int tid = threadIdx.x;
    const int i0 = blockIdx.y * 64;
    const int j0 = blockIdx.x * 64;
    const int tx = tid & 15, ty = tid >> 4;
    const int kr = tid >> 4;
    const int ic = (tid & 15) << 2;

    float acc[4][4];
#pragma unroll
    for (int r = 0; r < 4; r++)
#pragma unroll
        for (int c = 0; c < 4; c++) acc[r][c] = 0.f;

    for (int k0 = 0; k0 < K; k0 += 16) {
        *(float4*)&As[kr][ic] = *(const float4*)(A  + (long)(k0 + kr) * lda + i0 + ic);
        *(float4*)&Bs[kr][ic] = *(const float4*)(Bx + (long)(k0 + kr) * ldb + j0 + ic);
        __syncthreads();
#pragma unroll
        for (int kk = 0; kk < 16; kk++) {
            float av[4], bv[4];
#pragma unroll
            for (int r = 0; r < 4; r++) av[r] = As[kk][ty * 4 + r];
#pragma unroll
            for (int c = 0; c < 4; c++) bv[c] = Bs[kk][tx * 4 + c];
#pragma unroll
            for (int r = 0; r < 4; r++)
#pragma unroll
                for (int c = 0; c < 4; c++) acc[r][c] += av[r] * bv[c];
        }
        __syncthreads();
    }
#pragma unroll
    for (int r = 0; r < 4; r++) {
        const int i = i0 + ty * 4 + r;
#pragma unroll
        for (int c = 0; c < 4; c++)
            Cm[(long)i * ldc + j0 + tx * 4 + c] = acc[r][c];
    }
}

// ---------------- L2 normalize + emit fp16 ----------------------------------
__global__ __launch_bounds__(256) void l2norm(const float* __restrict__ z,
                                              __half* __restrict__ zh)
{
    const int row = blockIdx.x;
    const float* p = z + (long)row * Cc;
    float s = 0.f;
    for (int c = threadIdx.x; c < Cc; c += 256) { float v = p[c]; s += v * v; }
    __shared__ float red[256];
    red[threadIdx.x] = s;
    __syncthreads();
    for (int st = 128; st > 0; st >>= 1) {
        if (threadIdx.x < st) red[threadIdx.x] += red[threadIdx.x + st];
        __syncthreads();
    }
    const float inv = 1.f / fmaxf(sqrtf(red[0]), 1e-12f);
    for (int c = threadIdx.x * 2; c < Cc; c += 512) {
        __half2 h = __floats2half2_rn(p[c] * inv, p[c + 1] * inv);
        *(uint32_t*)&zh[(long)row * Cc + c] = *(uint32_t*)&h;
    }
}

// ---------------- fused attention (reads fused KV, fp16 out) -----------------
__global__ __launch_bounds__(128) void attn_kernel(
    const float* __restrict__ q, const float* __restrict__ kv,
    __half* __restrict__ oh)
{
    const int bh = blockIdx.x;
    const int b = bh / Hh;
    const int h = bh % Hh;
    const int n = blockIdx.y * 128 + threadIdx.x;

    __shared__ float ks[Mm][Dd];
    __shared__ float vs[Mm][Dd];
    for (int idx = threadIdx.x; idx < Mm * (Dd / 4); idx += 128) {
        const int m = idx >> 4;
        const int d4 = (idx & 15) << 2;
        const long base = ((long)b * Mm + m) * (2 * Cc) + h * Dd + d4;
        *(float4*)&ks[m][d4] = *(const float4*)&kv[base];
        *(float4*)&vs[m][d4] = *(const float4*)&kv[base + Cc];
    }
    __syncthreads();

    float qd[Dd];
    const float* qp = q + ((long)b * Nn + n) * Cc + h * Dd;
#pragma unroll
    for (int d4 = 0; d4 < Dd; d4 += 4) {
        float4 t = *(const float4*)(qp + d4);
        qd[d4] = t.x; qd[d4 + 1] = t.y; qd[d4 + 2] = t.z; qd[d4 + 3] = t.w;
    }

    float oacc[Dd];
#pragma unroll
    for (int d = 0; d < Dd; d++) oacc[d] = 0.f;
    float mmax = -1e30f, lsum = 0.f;
    const float scale = 0.125f;

#pragma unroll
    for (int c0 = 0; c0 < Mm; c0 += 16) {
        float s[16];
#pragma unroll
        for (int i = 0; i < 16; i++) {
            float acc = 0.f;
#pragma unroll
            for (int d = 0; d < Dd; d++) acc += qd[d] * ks[c0 + i][d];
            s[i] = acc * scale;
        }
        float cmax = s[0];
#pragma unroll
        for (int i = 1; i < 16; i++) cmax = fmaxf(cmax, s[i]);
        const float nm = fmaxf(mmax, cmax);
        const float corr = __expf(mmax - nm);
        lsum *= corr;
#pragma unroll
        for (int d = 0; d < Dd; d++) oacc[d] *= corr;
#pragma unroll
        for (int i = 0; i < 16; i++) {
            const float p = __expf(s[i] - nm);
            lsum += p;
#pragma unroll
            for (int d = 0; d < Dd; d++) oacc[d] += p * vs[c0 + i][d];
        }
        mmax = nm;
    }

    const float inv = 1.f / lsum;
    const long ob = ((long)b * Nn + n) * Cc + h * Dd;
#pragma unroll
    for (int d4 = 0; d4 < Dd; d4 += 4) {
        __half2 h0 = __floats2half2_rn(oacc[d4] * inv, oacc[d4 + 1] * inv);
        __half2 h1 = __floats2half2_rn(oacc[d4 + 2] * inv, oacc[d4 + 3] * inv);
        *(uint2*)&oh[ob + d4] = make_uint2(*(uint32_t*)&h0, *(uint32_t*)&h1);
    }
}

// ---------------------------------------------------------------------------
extern "C" void kernel_launch(void* const* d_in, const int* in_sizes, int n_in,
                              void* d_out, int out_size)
{
    (void)in_sizes; (void)n_in; (void)out_size;
    const float* x  = (const float*)d_in[0];
    const float* Wc = (const float*)d_in[1];
    const float* bc = (const float*)d_in[2];
    const float* Wq = (const float*)d_in[3];
    const float* bq = (const float*)d_in[4];
    const float* Wk = (const float*)d_in[5];
    const float* bk = (const float*)d_in[6];
    const float* Wv = (const float*)d_in[7];
    const float* bv = (const float*)d_in[8];
    const float* Wp = (const float*)d_in[9];
    const float* bp = (const float*)d_in[10];
    float* out = (float*)d_out;

    float *ct, *z, *q, *kv, *bkv;
    __half *xh, *oh, *zh, *wh, *wcl;
    cudaGetSymbolAddress((void**)&ct,  g_ct);
    cudaGetSymbolAddress((void**)&z,   g_z);
    cudaGetSymbolAddress((void**)&q,   g_q);
    cudaGetSymbolAddress((void**)&kv,  g_kv);
    cudaGetSymbolAddress((void**)&bkv, g_bkv);
    cudaGetSymbolAddress((void**)&xh,  g_xh);
    cudaGetSymbolAddress((void**)&oh,  g_oh);
    cudaGetSymbolAddress((void**)&zh,  g_zh);
    cudaGetSymbolAddress((void**)&wh,  g_wh);
    cudaGetSymbolAddress((void**)&wcl, g_wcl);

    constexpr int SMEM_S128 = 2 * (128 * 64 + 128 * 64);      // 32 KB (single)
    constexpr int SMEM_D64  = 2 * (128 * 64 + 2 * 64 * 64);   // 32 KB (2-term)
    cudaFuncSetAttribute(gemm_tc<128, 0, false>,
        cudaFuncAttributeMaxDynamicSharedMemorySize, SMEM_S128);
    cudaFuncSetAttribute(gemm_tc<64, 1, true>,
        cudaFuncAttributeMaxDynamicSharedMemorySize, SMEM_D64);

    const int IN = Bb * Nn;   // 32768
    const int IM = Bb * Mm;   // 2048

    // 0. convert: x -> fp16; Wc -> fp16 hi+lo; Wq/Wk/Wv/Wp -> fp16 hi
    {
        int n4 = IN * Cc / 4;
        cvt_h<<<(n4 + 255) / 256, 256>>>((const float4*)x, (uint2*)xh, n4);
        n4 = Mm * Cc / 4;
        cvt_hl<<<(n4 + 255) / 256, 256>>>((const float4*)Wc,
            (uint2*)(wh + W_OFF_C), (uint2*)wcl, n4);
        n4 = Cc * Cc / 4;
        cvt_h<<<(n4 + 255) / 256, 256>>>((const float4*)Wq, (uint2*)(wh + W_OFF_Q), n4);
        cvt_h<<<(n4 + 255) / 256, 256>>>((const float4*)Wk, (uint2*)(wh + W_OFF_K), n4);
        cvt_h<<<(n4 + 255) / 256, 256>>>((const float4*)Wv, (uint2*)(wh + W_OFF_V), n4);
        cvt_h<<<(n4 + 255) / 256, 256>>>((const float4*)Wp, (uint2*)(wh + W_OFF_P), n4);
        // concat bias for fused KV GEMM (async d2d copies are capture-legal)
        cudaMemcpyAsync(bkv, bk, Cc * sizeof(float), cudaMemcpyDeviceToDevice);
        cudaMemcpyAsync(bkv + Cc, bv, Cc * sizeof(float), cudaMemcpyDeviceToDevice);
    }

    // 1. cluster logits: ct = sigmoid(x @ Wc^T + bc)/N  (2-term for precision)
    gemm_tc<64, 1, true><<<dim3(1, IN / 128), 256, SMEM_D64>>>(
        xh, wh + W_OFF_C, wcl, bc, ct, Mm);

    // 2. z[b] = ct[b]^T @ x[b]
    gemm_tn<<<dim3(Cc / 64, Mm / 64, Bb), 256>>>(
        ct, x, z, Mm, Cc, Nn, Mm, Cc, Cc,
        (long)Nn * Mm, (long)Nn * Cc, (long)Mm * Cc);

    // 3. L2 normalize z rows -> fp16
    l2norm<<<IM, 256>>>(z, zh);

    // 4. Q = x @ Wq^T + bq  (single fp16 MMA)
    gemm_tc<128, 0, false><<<dim3(Cc / 128, IN / 128), 256, SMEM_S128>>>(
        xh, wh + W_OFF_Q, nullptr, bq, q, Cc);

    // 5. fused KV = z @ [Wk|Wv]^T + [bk|bv]   (2048 x 1536, single MMA)
    gemm_tc<128, 0, false><<<dim3(2 * Cc / 128, IM / 128), 256, SMEM_S128>>>(
        zh, wh + W_OFF_K, nullptr, bkv, kv, 2 * Cc);

    // 6. fused attention -> o (fp16)
    attn_kernel<<<dim3(Bb * Hh, Nn / 128), 128>>>(q, kv, oh);

    // 7. out = o @ Wp^T + bp  (single fp16 MMA)
    gemm_tc<128, 0, false><<<dim3(Cc / 128, IN / 128), 256, SMEM_S128>>>(
        oh, wh + W_OFF_P, nullptr, bp, out, Cc);
}

// round 12
// speedup vs baseline: 6.4791x; 1.7884x over previous
#include <cuda_runtime.h>
#include <cuda_fp16.h>
#include <math.h>
#include <stdint.h>

#define Bb 32
#define Nn 1024
#define Cc 768
#define Mm 64
#define Hh 12
#define Dd 64

// ---------------- scratch (__device__ globals per allocation contract) ------
__device__ float g_ct[Bb * Nn * Mm];
__device__ float g_z [Bb * Mm * Cc];
__device__ float g_bkv[2 * Cc];

__device__ __half g_xh [Bb * Nn * Cc];     // x  fp16
__device__ __half g_qh [Bb * Nn * Cc];     // q  fp16 (written by Q-proj)
__device__ __half g_kvh[Bb * Mm * 2 * Cc]; // K|V fp16 (written by KV-proj)
__device__ __half g_oh [Bb * Nn * Cc];     // attn out fp16
__device__ __half g_zh [Bb * Mm * Cc];
#define W_OFF_C 0
#define W_OFF_Q (Mm * Cc)
#define W_OFF_K (W_OFF_Q + Cc * Cc)
#define W_OFF_V (W_OFF_K + Cc * Cc)
#define W_OFF_P (W_OFF_V + Cc * Cc)
#define W_TOTAL (W_OFF_P + Cc * Cc)
__device__ __half g_wh[W_TOTAL];
__device__ __half g_wcl[Mm * Cc];          // lo part for Wc (2-term cluster)

// ---------------- helpers ---------------------------------------------------
__device__ __forceinline__ uint32_t smem_u32(const void* p) {
    uint32_t a;
    asm("{ .reg .u64 t; cvta.to.shared.u64 t, %1; cvt.u32.u64 %0, t; }"
        : "=r"(a) : "l"(p));
    return a;
}
#define CP16(saddr, gaddr) \
    asm volatile("cp.async.cg.shared.global [%0], [%1], 16;" \
                 :: "r"(saddr), "l"(gaddr))
#define CP_COMMIT() asm volatile("cp.async.commit_group;")
#define CP_WAIT(n)  asm volatile("cp.async.wait_group %0;" :: "n"(n))

#define LDSM4(r, a) \
    asm volatile("ldmatrix.sync.aligned.m8n8.x4.shared.b16 {%0,%1,%2,%3}, [%4];" \
        : "=r"((r)[0]), "=r"((r)[1]), "=r"((r)[2]), "=r"((r)[3]) : "r"(a))
#define LDSM4T(r, a) \
    asm volatile("ldmatrix.sync.aligned.m8n8.x4.trans.shared.b16 {%0,%1,%2,%3}, [%4];" \
        : "=r"((r)[0]), "=r"((r)[1]), "=r"((r)[2]), "=r"((r)[3]) : "r"(a))

#define MMA_F16(c, a, b0, b1) \
    asm volatile("mma.sync.aligned.m16n8k16.row.col.f32.f16.f16.f32 " \
        "{%0,%1,%2,%3},{%4,%5,%6,%7},{%8,%9},{%0,%1,%2,%3};" \
        : "+f"((c)[0]), "+f"((c)[1]), "+f"((c)[2]), "+f"((c)[3]) \
        : "r"((a)[0]), "r"((a)[1]), "r"((a)[2]), "r"((a)[3]), "r"(b0), "r"(b1))

__device__ __forceinline__ void wsplit2(float a, float b, uint32_t& hi, uint32_t& lo) {
    __half ha = __float2half_rn(a), hb = __float2half_rn(b);
    float ra = a - __half2float(ha);
    float rb = b - __half2float(hb);
    __half2 H, L;
    H.x = ha; H.y = hb;
    L.x = __float2half_rn(ra); L.y = __float2half_rn(rb);
    hi = *(uint32_t*)&H; lo = *(uint32_t*)&L;
}

// ---------------- converters -------------------------------------------------
__global__ __launch_bounds__(256) void cvt_h(const float4* __restrict__ in,
                                             uint2* __restrict__ hi, int n4) {
    int i = blockIdx.x * 256 + threadIdx.x;
    if (i >= n4) return;
    float4 a = in[i];
    __half2 h0 = __floats2half2_rn(a.x, a.y);
    __half2 h1 = __floats2half2_rn(a.z, a.w);
    hi[i] = make_uint2(*(uint32_t*)&h0, *(uint32_t*)&h1);
}
__global__ __launch_bounds__(256) void cvt_hl(const float4* __restrict__ in,
                                              uint2* __restrict__ hi,
                                              uint2* __restrict__ lo, int n4) {
    int i = blockIdx.x * 256 + threadIdx.x;
    if (i >= n4) return;
    float4 a = in[i];
    uint32_t h0, l0, h1, l1;
    wsplit2(a.x, a.y, h0, l0);
    wsplit2(a.z, a.w, h1, l1);
    hi[i] = make_uint2(h0, h1);
    lo[i] = make_uint2(l0, l1);
}

// ---------------- fp16 GEMM NT via mma.sync ---------------------------------
// C(I,J) = A(I,768)·B(J,768)^T + bias [, sigmoid/N]. OUTH: fp16 output.
template <int TN, int MODE, bool TWO, bool OUTH>
__global__ __launch_bounds__(256) void gemm_tc(
    const __half* __restrict__ Ah,
    const __half* __restrict__ Bh, const __half* __restrict__ Bl,
    const float* __restrict__ bias, void* __restrict__ CoutV, int J)
{
    constexpr int K = Cc;
    constexpr int KC = 32;
    constexpr int NCH = K / KC;        // 24
    constexpr int ABY = 128 * 64;      // 8 KB
    constexpr int BBY = TN * 64;
    constexpr int STAGE = ABY + (TWO ? 2 : 1) * BBY;
    constexpr int TNW = TN / 4;
    constexpr int NT = TNW / 8;
    constexpr int NP = NT / 2;

    extern __shared__ char smem[];
    const uint32_t s0 = smem_u32(smem);
    const uint32_t sb[2] = {s0, s0 + STAGE};

    const int tid = threadIdx.x;
    const int wid = tid >> 5;
    const int lane = tid & 31;
    const int wm = wid & 1;
    const int wn = wid >> 1;
    const int i0 = blockIdx.y * 128;
    const int j0 = blockIdx.x * TN;

    float acc[4][NT][4];
#pragma unroll
    for (int a = 0; a < 4; a++)
#pragma unroll
        for (int b = 0; b < NT; b++)
#pragma unroll
            for (int c = 0; c < 4; c++) acc[a][b][c] = 0.f;

    auto prefetch = [&](int ch, int s) {
        const uint32_t base = sb[s];
        const int k0 = ch * KC;
#pragma unroll
        for (int it = 0; it < 2; it++) {
            int id = tid + it * 256;
            int row = id >> 2, c = id & 3;
            uint32_t off = row * 64 + (((c ^ (row >> 1)) & 3) << 4);
            CP16(base + off, Ah + (size_t)(i0 + row) * K + k0 + c * 8);
        }
#pragma unroll
        for (int it = 0; it < (TN * 4) / 256; it++) {
            int id = tid + it * 256;
            int row = id >> 2, c = id & 3;
            uint32_t off = row * 64 + (((c ^ (row >> 1)) & 3) << 4);
            CP16(base + ABY + off, Bh + (size_t)(j0 + row) * K + k0 + c * 8);
            if constexpr (TWO)
                CP16(base + ABY + BBY + off,
                     Bl + (size_t)(j0 + row) * K + k0 + c * 8);
        }
    };

    auto compute = [&](int s) {
        const uint32_t ab = sb[s];
        const uint32_t bhb = ab + ABY, blb = bhb + BBY;
#pragma unroll
        for (int ks = 0; ks < 2; ks++) {
            uint32_t BH[NP][4], BL[NP][4];
#pragma unroll
            for (int p = 0; p < NP; p++) {
                int row = wn * TNW + p * 16 + (lane & 15);
                int ch = ks * 2 + (lane >> 4);
                uint32_t off = row * 64 + (((ch ^ (row >> 1)) & 3) << 4);
                LDSM4(BH[p], bhb + off);
                if constexpr (TWO) LDSM4(BL[p], blb + off);
            }
#pragma unroll
            for (int mt = 0; mt < 4; mt++) {
                int row = wm * 64 + mt * 16 + (lane & 15);
                int ch = ks * 2 + (lane >> 4);
                uint32_t off = row * 64 + (((ch ^ (row >> 1)) & 3) << 4);
                uint32_t AH[4];
                LDSM4(AH, ab + off);
#pragma unroll
                for (int nt = 0; nt < NT; nt++) {
                    uint32_t b0h = BH[nt >> 1][nt & 1], b1h = BH[nt >> 1][(nt & 1) + 2];
                    MMA_F16(acc[mt][nt], AH, b0h, b1h);
                    if constexpr (TWO) {
                        uint32_t b0l = BL[nt >> 1][nt & 1];
                        uint32_t b1l = BL[nt >> 1][(nt & 1) + 2];
                        MMA_F16(acc[mt][nt], AH, b0l, b1l);
                    }
                }
            }
        }
    };

    prefetch(0, 0);
    CP_COMMIT();
    for (int ch = 0; ch < NCH; ch++) {
        if (ch + 1 < NCH) {
            prefetch(ch + 1, (ch + 1) & 1);
            CP_COMMIT();
            CP_WAIT(1);
        } else {
            CP_WAIT(0);
        }
        __syncthreads();
        compute(ch & 1);
        __syncthreads();
    }

#pragma unroll
    for (int mt = 0; mt < 4; mt++) {
        const int gr = i0 + wm * 64 + mt * 16 + (lane >> 2);
#pragma unroll
        for (int nt = 0; nt < NT; nt++) {
            const int gc = j0 + wn * TNW + nt * 8 + (lane & 3) * 2;
            const float b0 = __ldg(bias + gc), b1 = __ldg(bias + gc + 1);
            float v0 = acc[mt][nt][0] + b0, v1 = acc[mt][nt][1] + b1;
            float v2 = acc[mt][nt][2] + b0, v3 = acc[mt][nt][3] + b1;
            if (MODE == 1) {
                v0 = 1.f / (1.f + __expf(-v0)) * (1.f / Nn);
                v1 = 1.f / (1.f + __expf(-v1)) * (1.f / Nn);
                v2 = 1.f / (1.f + __expf(-v2)) * (1.f / Nn);
                v3 = 1.f / (1.f + __expf(-v3)) * (1.f / Nn);
            }
            if constexpr (OUTH) {
                __half* Ch = (__half*)CoutV;
                __half2 h0 = __floats2half2_rn(v0, v1);
                __half2 h1 = __floats2half2_rn(v2, v3);
                *(__half2*)(Ch + (size_t)gr * J + gc) = h0;
                *(__half2*)(Ch + (size_t)(gr + 8) * J + gc) = h1;
            } else {
                float* Cf = (float*)CoutV;
                *(float2*)(Cf + (size_t)gr * J + gc) = make_float2(v0, v1);
                *(float2*)(Cf + (size_t)(gr + 8) * J + gc) = make_float2(v2, v3);
            }
        }
    }
}

// ---------------- batched TN GEMM (z = ct^T @ x), fp32 SIMT ------------------
__global__ __launch_bounds__(256) void gemm_tn(
    const float* __restrict__ A, const float* __restrict__ Bx,
    float* __restrict__ Cm,
    int I, int J, int K, int lda, int ldb, int ldc,
    long sA, long sB, long sC)
{
    A  += (long)blockIdx.z * sA;
    Bx += (long)blockIdx.z * sB;
    Cm += (long)blockIdx.z * sC;

    __shared__ float As[16][64];
    __shared__ float Bs[16][64];
    const int tid = threadIdx.x;
    const int i0 = blockIdx.y * 64;
    const int j0 = blockIdx.x * 64;
    const int tx = tid & 15, ty = tid >> 4;
    const int kr = tid >> 4;
    const int ic = (tid & 15) << 2;

    float acc[4][4];
#pragma unroll
    for (int r = 0; r < 4; r++)
#pragma unroll
        for (int c = 0; c < 4; c++) acc[r][c] = 0.f;

    for (int k0 = 0; k0 < K; k0 += 16) {
        *(float4*)&As[kr][ic] = *(const float4*)(A  + (long)(k0 + kr) * lda + i0 + ic);
        *(float4*)&Bs[kr][ic] = *(const float4*)(Bx + (long)(k0 + kr) * ldb + j0 + ic);
        __syncthreads();
#pragma unroll
        for (int kk = 0; kk < 16; kk++) {
            float av[4], bv[4];
#pragma unroll
            for (int r = 0; r < 4; r++) av[r] = As[kk][ty * 4 + r];
#pragma unroll
            for (int c = 0; c < 4; c++) bv[c] = Bs[kk][tx * 4 + c];
#pragma unroll
            for (int r = 0; r < 4; r++)
#pragma unroll
                for (int c = 0; c < 4; c++) acc[r][c] += av[r] * bv[c];
        }
        __syncthreads();
    }
#pragma unroll
    for (int r = 0; r < 4; r++) {
        const int i = i0 + ty * 4 + r;
#pragma unroll
        for (int c = 0; c < 4; c++)
            Cm[(long)i * ldc + j0 + tx * 4 + c] = acc[r][c];
    }
}

// ---------------- L2 normalize + emit fp16 ----------------------------------
__global__ __launch_bounds__(256) void l2norm(const float* __restrict__ z,
                                              __half* __restrict__ zh)
{
    const int row = blockIdx.x;
    const float* p = z + (long)row * Cc;
    float s = 0.f;
    for (int c = threadIdx.x; c < Cc; c += 256) { float v = p[c]; s += v * v; }
    __shared__ float red[256];
    red[threadIdx.x] = s;
    __syncthreads();
    for (int st = 128; st > 0; st >>= 1) {
        if (threadIdx.x < st) red[threadIdx.x] += red[threadIdx.x + st];
        __syncthreads();
    }
    const float inv = 1.f / fmaxf(sqrtf(red[0]), 1e-12f);
    for (int c = threadIdx.x * 2; c < Cc; c += 512) {
        __half2 h = __floats2half2_rn(p[c] * inv, p[c + 1] * inv);
        *(uint32_t*)&zh[(long)row * Cc + c] = *(uint32_t*)&h;
    }
}

// ---------------- tensor-core attention --------------------------------------
// CTA: one (b,h), 128 queries. 8 warps x 16 query rows.
// S = Q·K^T (MMA) -> softmax in fragments -> P·V (MMA, P stays in registers).
__global__ __launch_bounds__(256) void attn_tc(
    const __half* __restrict__ qh, const __half* __restrict__ kvh,
    __half* __restrict__ oh)
{
    const int bh = blockIdx.x;
    const int b = bh / Hh;
    const int h = bh % Hh;
    const int n0 = blockIdx.y * 128;

    __shared__ __align__(128) char smem[32768];
    const uint32_t sq = smem_u32(smem);
    const uint32_t sk = sq + 16384;
    const uint32_t sv = sk + 8192;

    const int tid = threadIdx.x;
    const int wid = tid >> 5;
    const int lane = tid & 31;

    // stage Q (128x64), K (64x64), V (64x64) fp16, 128B rows, xor-8 swizzle
#pragma unroll
    for (int it = 0; it < 4; it++) {
        int id = tid + it * 256;
        int row = id >> 3, c = id & 7;
        uint32_t off = row * 128 + (((c ^ row) & 7) << 4);
        CP16(sq + off, qh + (size_t)(b * Nn + n0 + row) * Cc + h * Dd + c * 8);
    }
#pragma unroll
    for (int it = 0; it < 2; it++) {
        int id = tid + it * 256;
        int row = id >> 3, c = id & 7;
        uint32_t off = row * 128 + (((c ^ row) & 7) << 4);
        const size_t base = (size_t)(b * Mm + row) * (2 * Cc) + h * Dd + c * 8;
        CP16(sk + off, kvh + base);
        CP16(sv + off, kvh + base + Cc);
    }
    CP_COMMIT();
    CP_WAIT(0);
    __syncthreads();

    // S = Q K^T : warp rows wid*16..+15, all 64 keys (8 n8-tiles)
    float s[8][4];
#pragma unroll
    for (int t = 0; t < 8; t++)
#pragma unroll
        for (int c = 0; c < 4; c++) s[t][c] = 0.f;

#pragma unroll
    for (int kf = 0; kf < 4; kf++) {
        const int ch = kf * 2 + (lane >> 4);
        uint32_t A[4];
        {
            int row = wid * 16 + (lane & 15);
            LDSM4(A, sq + row * 128 + (((ch ^ row) & 7) << 4));
        }
        uint32_t Bk[4][4];
#pragma unroll
        for (int p = 0; p < 4; p++) {
            int row = p * 16 + (lane & 15);
            LDSM4(Bk[p], sk + row * 128 + (((ch ^ row) & 7) << 4));
        }
#pragma unroll
        for (int nt = 0; nt < 8; nt++)
            MMA_F16(s[nt], A, Bk[nt >> 1][nt & 1], Bk[nt >> 1][(nt & 1) + 2]);
    }

    // softmax over 64 cols; rows r=wid*16+(lane>>2) and r+8
    const float scale = 0.125f;
    float m0 = -1e30f, m1 = -1e30f;
#pragma unroll
    for (int t = 0; t < 8; t++) {
#pragma unroll
        for (int c = 0; c < 4; c++) s[t][c] *= scale;
        m0 = fmaxf(m0, fmaxf(s[t][0], s[t][1]));
        m1 = fmaxf(m1, fmaxf(s[t][2], s[t][3]));
    }
    m0 = fmaxf(m0, __shfl_xor_sync(0xffffffff, m0, 1));
    m0 = fmaxf(m0, __shfl_xor_sync(0xffffffff, m0, 2));
    m1 = fmaxf(m1, __shfl_xor_sync(0xffffffff, m1, 1));
    m1 = fmaxf(m1, __shfl_xor_sync(0xffffffff, m1, 2));

    float l0 = 0.f, l1 = 0.f;
    uint32_t P[4][4];   // A-fragments for P·V, built in-register
#pragma unroll
    for (int t = 0; t < 8; t++) {
        float p0 = __expf(s[t][0] - m0);
        float p1 = __expf(s[t][1] - m0);
        float p2 = __expf(s[t][2] - m1);
        float p3 = __expf(s[t][3] - m1);
        l0 += p0 + p1;
        l1 += p2 + p3;
        __half2 h01 = __floats2half2_rn(p0, p1);
        __half2 h23 = __floats2half2_rn(p2, p3);
        P[t >> 1][(t & 1) * 2 + 0] = *(uint32_t*)&h01;
        P[t >> 1][(t & 1) * 2 + 1] = *(uint32_t*)&h23;
    }
    l0 += __shfl_xor_sync(0xffffffff, l0, 1);
    l0 += __shfl_xor_sync(0xffffffff, l0, 2);
    l1 += __shfl_xor_sync(0xffffffff, l1, 1);
    l1 += __shfl_xor_sync(0xffffffff, l1, 2);

    // O = P V  (V loaded col-major via ldmatrix.trans)
    float o[8][4];
#pragma unroll
    for (int t = 0; t < 8; t++)
#pragma unroll
        for (int c = 0; c < 4; c++) o[t][c] = 0.f;

#pragma unroll
    for (int kf = 0; kf < 4; kf++) {
#pragma unroll
        for (int dt = 0; dt < 4; dt++) {
            uint32_t VF[4];
            int row = kf * 16 + (lane & 15);
            int ch = dt * 2 + (lane >> 4);
            LDSM4T(VF, sv + row * 128 + (((ch ^ row) & 7) << 4));
            MMA_F16(o[dt * 2],     P[kf], VF[0], VF[1]);
            MMA_F16(o[dt * 2 + 1], P[kf], VF[2], VF[3]);
        }
    }

    // epilogue: normalize rows, write fp16 o
    const float inv0 = 1.f / l0, inv1 = 1.f / l1;
    const int r = wid * 16 + (lane >> 2);
    const size_t ob = (size_t)(b * Nn + n0 + r) * Cc + h * Dd;
#pragma unroll
    for (int t = 0; t < 8; t++) {
        const int col = t * 8 + (lane & 3) * 2;
        __half2 h0 = __floats2half2_rn(o[t][0] * inv0, o[t][1] * inv0);
        __half2 h1 = __floats2half2_rn(o[t][2] * inv1, o[t][3] * inv1);
        *(__half2*)(oh + ob + col) = h0;
        *(__half2*)(oh + ob + 8 * Cc + col) = h1;
    }
}

// ---------------------------------------------------------------------------
extern "C" void kernel_launch(void* const* d_in, const int* in_sizes, int n_in,
                              void* d_out, int out_size)
{
    (void)in_sizes; (void)n_in; (void)out_size;
    const float* x  = (const float*)d_in[0];
    const float* Wc = (const float*)d_in[1];
    const float* bc = (const float*)d_in[2];
    const float* Wq = (const float*)d_in[3];
    const float* bq = (const float*)d_in[4];
    const float* Wk = (const float*)d_in[5];
    const float* bk = (const float*)d_in[6];
    const float* Wv = (const float*)d_in[7];
    const float* bv = (const float*)d_in[8];
    const float* Wp = (const float*)d_in[9];
    const float* bp = (const float*)d_in[10];
    float* out = (float*)d_out;

    float *ct, *z, *bkv;
    __half *xh, *qh, *kvh, *oh, *zh, *wh, *wcl;
    cudaGetSymbolAddress((void**)&ct,  g_ct);
    cudaGetSymbolAddress((void**)&z,   g_z);
    cudaGetSymbolAddress((void**)&bkv, g_bkv);
    cudaGetSymbolAddress((void**)&xh,  g_xh);
    cudaGetSymbolAddress((void**)&qh,  g_qh);
    cudaGetSymbolAddress((void**)&kvh, g_kvh);
    cudaGetSymbolAddress((void**)&oh,  g_oh);
    cudaGetSymbolAddress((void**)&zh,  g_zh);
    cudaGetSymbolAddress((void**)&wh,  g_wh);
    cudaGetSymbolAddress((void**)&wcl, g_wcl);

    constexpr int SMEM_S128 = 2 * (128 * 64 + 128 * 64);      // 32 KB
    constexpr int SMEM_D64  = 2 * (128 * 64 + 2 * 64 * 64);   // 32 KB
    cudaFuncSetAttribute(gemm_tc<128, 0, false, false>,
        cudaFuncAttributeMaxDynamicSharedMemorySize, SMEM_S128);
    cudaFuncSetAttribute(gemm_tc<128, 0, false, true>,
        cudaFuncAttributeMaxDynamicSharedMemorySize, SMEM_S128);
    cudaFuncSetAttribute(gemm_tc<64, 1, true, false>,
        cudaFuncAttributeMaxDynamicSharedMemorySize, SMEM_D64);

    const int IN = Bb * Nn;   // 32768
    const int IM = Bb * Mm;   // 2048

    // 0. convert: x -> fp16; Wc -> fp16 hi+lo; Wq/Wk/Wv/Wp -> fp16 hi
    {
        int n4 = IN * Cc / 4;
        cvt_h<<<(n4 + 255) / 256, 256>>>((const float4*)x, (uint2*)xh, n4);
        n4 = Mm * Cc / 4;
        cvt_hl<<<(n4 + 255) / 256, 256>>>((const float4*)Wc,
            (uint2*)(wh + W_OFF_C), (uint2*)wcl, n4);
        n4 = Cc * Cc / 4;
        cvt_h<<<(n4 + 255) / 256, 256>>>((const float4*)Wq, (uint2*)(wh + W_OFF_Q), n4);
        cvt_h<<<(n4 + 255) / 256, 256>>>((const float4*)Wk, (uint2*)(wh + W_OFF_K), n4);
        cvt_h<<<(n4 + 255) / 256, 256>>>((const float4*)Wv, (uint2*)(wh + W_OFF_V), n4);
        cvt_h<<<(n4 + 255) / 256, 256>>>((const float4*)Wp, (uint2*)(wh + W_OFF_P), n4);
        cudaMemcpyAsync(bkv, bk, Cc * sizeof(float), cudaMemcpyDeviceToDevice);
        cudaMemcpyAsync(bkv + Cc, bv, Cc * sizeof(float), cudaMemcpyDeviceToDevice);
    }

    // 1. cluster logits: ct = sigmoid(x @ Wc^T + bc)/N  (2-term, fp32 out)
    gemm_tc<64, 1, true, false><<<dim3(1, IN / 128), 256, SMEM_D64>>>(
        xh, wh + W_OFF_C, wcl, bc, ct, Mm);

    // 2. z[b] = ct[b]^T @ x[b]
    gemm_tn<<<dim3(Cc / 64, Mm / 64, Bb), 256>>>(
        ct, x, z, Mm, Cc, Nn, Mm, Cc, Cc,
        (long)Nn * Mm, (long)Nn * Cc, (long)Mm * Cc);

    // 3. L2 normalize z rows -> fp16
    l2norm<<<IM, 256>>>(z, zh);

    // 4. Q = x @ Wq^T + bq  -> fp16
    gemm_tc<128, 0, false, true><<<dim3(Cc / 128, IN / 128), 256, SMEM_S128>>>(
        xh, wh + W_OFF_Q, nullptr, bq, qh, Cc);

    // 5. fused KV = z @ [Wk|Wv]^T + [bk|bv] -> fp16 (2048 x 1536)
    gemm_tc<128, 0, false, true><<<dim3(2 * Cc / 128, IM / 128), 256, SMEM_S128>>>(
        zh, wh + W_OFF_K, nullptr, bkv, kvh, 2 * Cc);

    // 6. tensor-core attention -> o (fp16)
    attn_tc<<<dim3(Bb * Hh, Nn / 128), 256>>>(qh, kvh, oh);

    // 7. out = o @ Wp^T + bp (fp32 out)
    gemm_tc<128, 0, false, false><<<dim3(Cc / 128, IN / 128), 256, SMEM_S128>>>(
        oh, wh + W_OFF_P, nullptr, bp, out, Cc);
}

// round 13
// speedup vs baseline: 7.9229x; 1.2228x over previous
#include <cuda_runtime.h>
#include <cuda_fp16.h>
#include <math.h>
#include <stdint.h>

#define Bb 32
#define Nn 1024
#define Cc 768
#define Mm 64
#define Hh 12
#define Dd 64

// ---------------- scratch (__device__ globals per allocation contract) ------
__device__ float g_z [Bb * Mm * Cc];
__device__ float g_bkv[2 * Cc];

__device__ __half g_cth[Bb * Nn * Mm];     // cluster weights fp16 (n-major)
__device__ __half g_xh [Bb * Nn * Cc];     // x  fp16
__device__ __half g_qh [Bb * Nn * Cc];     // q  fp16
__device__ __half g_kvh[Bb * Mm * 2 * Cc]; // K|V fp16
__device__ __half g_oh [Bb * Nn * Cc];     // attn out fp16
__device__ __half g_zh [Bb * Mm * Cc];
#define W_OFF_C 0
#define W_OFF_Q (Mm * Cc)
#define W_OFF_K (W_OFF_Q + Cc * Cc)
#define W_OFF_V (W_OFF_K + Cc * Cc)
#define W_OFF_P (W_OFF_V + Cc * Cc)
#define W_TOTAL (W_OFF_P + Cc * Cc)
__device__ __half g_wh[W_TOTAL];
__device__ __half g_wcl[Mm * Cc];          // lo part for Wc (2-term cluster)

// ---------------- helpers ---------------------------------------------------
__device__ __forceinline__ uint32_t smem_u32(const void* p) {
    uint32_t a;
    asm("{ .reg .u64 t; cvta.to.shared.u64 t, %1; cvt.u32.u64 %0, t; }"
        : "=r"(a) : "l"(p));
    return a;
}
#define CP16(saddr, gaddr) \
    asm volatile("cp.async.cg.shared.global [%0], [%1], 16;" \
                 :: "r"(saddr), "l"(gaddr))
#define CP_COMMIT() asm volatile("cp.async.commit_group;")
#define CP_WAIT(n)  asm volatile("cp.async.wait_group %0;" :: "n"(n))

#define LDSM4(r, a) \
    asm volatile("ldmatrix.sync.aligned.m8n8.x4.shared.b16 {%0,%1,%2,%3}, [%4];" \
        : "=r"((r)[0]), "=r"((r)[1]), "=r"((r)[2]), "=r"((r)[3]) : "r"(a))
#define LDSM4T(r, a) \
    asm volatile("ldmatrix.sync.aligned.m8n8.x4.trans.shared.b16 {%0,%1,%2,%3}, [%4];" \
        : "=r"((r)[0]), "=r"((r)[1]), "=r"((r)[2]), "=r"((r)[3]) : "r"(a))

#define MMA_F16(c, a, b0, b1) \
    asm volatile("mma.sync.aligned.m16n8k16.row.col.f32.f16.f16.f32 " \
        "{%0,%1,%2,%3},{%4,%5,%6,%7},{%8,%9},{%0,%1,%2,%3};" \
        : "+f"((c)[0]), "+f"((c)[1]), "+f"((c)[2]), "+f"((c)[3]) \
        : "r"((a)[0]), "r"((a)[1]), "r"((a)[2]), "r"((a)[3]), "r"(b0), "r"(b1))

__device__ __forceinline__ void wsplit2(float a, float b, uint32_t& hi, uint32_t& lo) {
    __half ha = __float2half_rn(a), hb = __float2half_rn(b);
    float ra = a - __half2float(ha);
    float rb = b - __half2float(hb);
    __half2 H, L;
    H.x = ha; H.y = hb;
    L.x = __float2half_rn(ra); L.y = __float2half_rn(rb);
    hi = *(uint32_t*)&H; lo = *(uint32_t*)&L;
}

// ---------------- converters -------------------------------------------------
__global__ __launch_bounds__(256) void cvt_h(const float4* __restrict__ in,
                                             uint2* __restrict__ hi, int n4) {
    int i = blockIdx.x * 256 + threadIdx.x;
    if (i >= n4) return;
    float4 a = in[i];
    __half2 h0 = __floats2half2_rn(a.x, a.y);
    __half2 h1 = __floats2half2_rn(a.z, a.w);
    hi[i] = make_uint2(*(uint32_t*)&h0, *(uint32_t*)&h1);
}
// fused converter for the four C x C weights (blockIdx.y selects)
__global__ __launch_bounds__(256) void cvt_w4(
    const float4* __restrict__ w0, const float4* __restrict__ w1,
    const float4* __restrict__ w2, const float4* __restrict__ w3,
    uint2* __restrict__ dst)
{
    const int n4 = Cc * Cc / 4;
    int i = blockIdx.x * 256 + threadIdx.x;
    if (i >= n4) return;
    const float4* src = (blockIdx.y == 0) ? w0 : (blockIdx.y == 1) ? w1
                      : (blockIdx.y == 2) ? w2 : w3;
    float4 a = src[i];
    __half2 h0 = __floats2half2_rn(a.x, a.y);
    __half2 h1 = __floats2half2_rn(a.z, a.w);
    dst[(size_t)blockIdx.y * n4 + i] =
        make_uint2(*(uint32_t*)&h0, *(uint32_t*)&h1);
}
__global__ __launch_bounds__(256) void cvt_hl(const float4* __restrict__ in,
                                              uint2* __restrict__ hi,
                                              uint2* __restrict__ lo, int n4) {
    int i = blockIdx.x * 256 + threadIdx.x;
    if (i >= n4) return;
    float4 a = in[i];
    uint32_t h0, l0, h1, l1;
    wsplit2(a.x, a.y, h0, l0);
    wsplit2(a.z, a.w, h1, l1);
    hi[i] = make_uint2(h0, h1);
    lo[i] = make_uint2(l0, l1);
}

// ---------------- fp16 GEMM NT via mma.sync ---------------------------------
// C(I,J) = A(I,768)·B(J,768)^T + bias [, sigmoid/N]. OUTH: fp16 output.
template <int TN, int MODE, bool TWO, bool OUTH>
__global__ __launch_bounds__(256) void gemm_tc(
    const __half* __restrict__ Ah,
    const __half* __restrict__ Bh, const __half* __restrict__ Bl,
    const float* __restrict__ bias, void* __restrict__ CoutV, int J)
{
    constexpr int K = Cc;
    constexpr int KC = 32;
    constexpr int NCH = K / KC;        // 24
    constexpr int ABY = 128 * 64;      // 8 KB
    constexpr int BBY = TN * 64;
    constexpr int STAGE = ABY + (TWO ? 2 : 1) * BBY;
    constexpr int TNW = TN / 4;
    constexpr int NT = TNW / 8;
    constexpr int NP = NT / 2;

    extern __shared__ char smem[];
    const uint32_t s0 = smem_u32(smem);
    const uint32_t sb[2] = {s0, s0 + STAGE};

    const int tid = threadIdx.x;
    const int wid = tid >> 5;
    const int lane = tid & 31;
    const int wm = wid & 1;
    const int wn = wid >> 1;
    const int i0 = blockIdx.y * 128;
    const int j0 = blockIdx.x * TN;

    float acc[4][NT][4];
#pragma unroll
    for (int a = 0; a < 4; a++)
#pragma unroll
        for (int b = 0; b < NT; b++)
#pragma unroll
            for (int c = 0; c < 4; c++) acc[a][b][c] = 0.f;

    auto prefetch = [&](int ch, int s) {
        const uint32_t base = sb[s];
        const int k0 = ch * KC;
#pragma unroll
        for (int it = 0; it < 2; it++) {
            int id = tid + it * 256;
            int row = id >> 2, c = id & 3;
            uint32_t off = row * 64 + (((c ^ (row >> 1)) & 3) << 4);
            CP16(base + off, Ah + (size_t)(i0 + row) * K + k0 + c * 8);
        }
#pragma unroll
        for (int it = 0; it < (TN * 4) / 256; it++) {
            int id = tid + it * 256;
            int row = id >> 2, c = id & 3;
            uint32_t off = row * 64 + (((c ^ (row >> 1)) & 3) << 4);
            CP16(base + ABY + off, Bh + (size_t)(j0 + row) * K + k0 + c * 8);
            if constexpr (TWO)
                CP16(base + ABY + BBY + off,
                     Bl + (size_t)(j0 + row) * K + k0 + c * 8);
        }
    };

    auto compute = [&](int s) {
        const uint32_t ab = sb[s];
        const uint32_t bhb = ab + ABY, blb = bhb + BBY;
#pragma unroll
        for (int ks = 0; ks < 2; ks++) {
            uint32_t BH[NP][4], BL[NP][4];
#pragma unroll
            for (int p = 0; p < NP; p++) {
                int row = wn * TNW + p * 16 + (lane & 15);
                int ch = ks * 2 + (lane >> 4);
                uint32_t off = row * 64 + (((ch ^ (row >> 1)) & 3) << 4);
                LDSM4(BH[p], bhb + off);
                if constexpr (TWO) LDSM4(BL[p], blb + off);
            }
#pragma unroll
            for (int mt = 0; mt < 4; mt++) {
                int row = wm * 64 + mt * 16 + (lane & 15);
                int ch = ks * 2 + (lane >> 4);
                uint32_t off = row * 64 + (((ch ^ (row >> 1)) & 3) << 4);
                uint32_t AH[4];
                LDSM4(AH, ab + off);
#pragma unroll
                for (int nt = 0; nt < NT; nt++) {
                    uint32_t b0h = BH[nt >> 1][nt & 1], b1h = BH[nt >> 1][(nt & 1) + 2];
                    MMA_F16(acc[mt][nt], AH, b0h, b1h);
                    if constexpr (TWO) {
                        uint32_t b0l = BL[nt >> 1][nt & 1];
                        uint32_t b1l = BL[nt >> 1][(nt & 1) + 2];
                        MMA_F16(acc[mt][nt], AH, b0l, b1l);
                    }
                }
            }
        }
    };

    prefetch(0, 0);
    CP_COMMIT();
    for (int ch = 0; ch < NCH; ch++) {
        if (ch + 1 < NCH) {
            prefetch(ch + 1, (ch + 1) & 1);
            CP_COMMIT();
            CP_WAIT(1);
        } else {
            CP_WAIT(0);
        }
        __syncthreads();
        compute(ch & 1);
        __syncthreads();
    }

#pragma unroll
    for (int mt = 0; mt < 4; mt++) {
        const int gr = i0 + wm * 64 + mt * 16 + (lane >> 2);
#pragma unroll
        for (int nt = 0; nt < NT; nt++) {
            const int gc = j0 + wn * TNW + nt * 8 + (lane & 3) * 2;
            const float b0 = __ldg(bias + gc), b1 = __ldg(bias + gc + 1);
            float v0 = acc[mt][nt][0] + b0, v1 = acc[mt][nt][1] + b1;
            float v2 = acc[mt][nt][2] + b0, v3 = acc[mt][nt][3] + b1;
            if (MODE == 1) {
                v0 = 1.f / (1.f + __expf(-v0)) * (1.f / Nn);
                v1 = 1.f / (1.f + __expf(-v1)) * (1.f / Nn);
                v2 = 1.f / (1.f + __expf(-v2)) * (1.f / Nn);
                v3 = 1.f / (1.f + __expf(-v3)) * (1.f / Nn);
            }
            if constexpr (OUTH) {
                __half* Ch = (__half*)CoutV;
                __half2 h0 = __floats2half2_rn(v0, v1);
                __half2 h1 = __floats2half2_rn(v2, v3);
                *(__half2*)(Ch + (size_t)gr * J + gc) = h0;
                *(__half2*)(Ch + (size_t)(gr + 8) * J + gc) = h1;
            } else {
                float* Cf = (float*)CoutV;
                *(float2*)(Cf + (size_t)gr * J + gc) = make_float2(v0, v1);
                *(float2*)(Cf + (size_t)(gr + 8) * J + gc) = make_float2(v2, v3);
            }
        }
    }
}

// ---------------- tensor-core z = ct^T @ x (per batch) ----------------------
// ct: (B, N=1024, M=64) fp16 n-major; x: (B, N, C) fp16; z: (B, M, C) fp32.
// Block: 64(M) x 128(J); 8 warps 4Mx2J, warp tile 16x64. K=N loop, KC=32.
// Both operands loaded with ldmatrix.trans (A from n-major ct, B col-major
// k-fragments from row-major x).
__global__ __launch_bounds__(256) void gemm_ctz(
    const __half* __restrict__ ct, const __half* __restrict__ xh,
    float* __restrict__ z)
{
    constexpr int KC = 32;
    constexpr int NCH = Nn / KC;     // 32
    constexpr int CTBY = 32 * 128;   // 4 KB (32 n-rows x 64 m fp16)
    constexpr int XBY  = 32 * 256;   // 8 KB (32 n-rows x 128 j fp16)
    constexpr int STAGE = CTBY + XBY;

    __shared__ __align__(128) char smem[2 * STAGE];
    const uint32_t s0 = smem_u32(smem);

    const int b = blockIdx.z;
    const int j0 = blockIdx.x * 128;
    const int tid = threadIdx.x;
    const int wid = tid >> 5, lane = tid & 31;
    const int m0 = (wid & 3) * 16;
    const int jw = (wid >> 2) * 64;

    float o[8][4];
#pragma unroll
    for (int t = 0; t < 8; t++)
#pragma unroll
        for (int c = 0; c < 4; c++) o[t][c] = 0.f;

    auto prefetch = [&](int chn, int s) {
        const uint32_t base = s0 + s * STAGE;
        const int k0 = chn * KC;
        {   // ct: 32 rows x 8 chunks = 256 -> 1/thread
            int r = tid >> 3, c = tid & 7;
            uint32_t off = r * 128 + (((c ^ (r & 7)) & 7) << 4);
            CP16(base + off, ct + ((size_t)b * Nn + k0 + r) * Mm + c * 8);
        }
#pragma unroll
        for (int it = 0; it < 2; it++) {  // x: 32 rows x 16 chunks = 512
            int id = tid + it * 256;
            int r = id >> 4, c = id & 15;
            uint32_t off = r * 256 + (((c ^ (r & 7)) & 15) << 4);
            CP16(base + CTBY + off,
                 xh + ((size_t)b * Nn + k0 + r) * Cc + j0 + c * 8);
        }
    };

    auto compute = [&](int s) {
        const uint32_t cb = s0 + s * STAGE, xb = cb + CTBY;
#pragma unroll
        for (int ks = 0; ks < 2; ks++) {
            const int row = ks * 16 + (lane & 7) + ((lane >> 4) & 1) * 8;
            uint32_t A[4];
            {
                int c = (m0 >> 3) + ((lane >> 3) & 1);
                LDSM4T(A, cb + row * 128 + (((c ^ (row & 7)) & 7) << 4));
            }
#pragma unroll
            for (int jt = 0; jt < 4; jt++) {
                uint32_t Bf[4];
                int c = ((jw + jt * 16) >> 3) + ((lane >> 3) & 1);
                LDSM4T(Bf, xb + row * 256 + (((c ^ (row & 7)) & 15) << 4));
                MMA_F16(o[jt * 2],     A, Bf[0], Bf[2]);
                MMA_F16(o[jt * 2 + 1], A, Bf[1], Bf[3]);
            }
        }
    };

    prefetch(0, 0);
    CP_COMMIT();
    for (int ch = 0; ch < NCH; ch++) {
        if (ch + 1 < NCH) {
            prefetch(ch + 1, (ch + 1) & 1);
            CP_COMMIT();
            CP_WAIT(1);
        } else {
            CP_WAIT(0);
        }
        __syncthreads();
        compute(ch & 1);
        __syncthreads();
    }

    const int r0 = m0 + (lane >> 2);
#pragma unroll
    for (int t = 0; t < 8; t++) {
        const int col = j0 + jw + t * 8 + (lane & 3) * 2;
        float* zp = z + ((size_t)b * Mm + r0) * Cc + col;
        *(float2*)zp = make_float2(o[t][0], o[t][1]);
        *(float2*)(zp + 8 * Cc) = make_float2(o[t][2], o[t][3]);
    }
}

// ---------------- L2 normalize + emit fp16 ----------------------------------
__global__ __launch_bounds__(256) void l2norm(const float* __restrict__ z,
                                              __half* __restrict__ zh)
{
    const int row = blockIdx.x;
    const float* p = z + (long)row * Cc;
    float s = 0.f;
    for (int c = threadIdx.x; c < Cc; c += 256) { float v = p[c]; s += v * v; }
    __shared__ float red[256];
    red[threadIdx.x] = s;
    __syncthreads();
    for (int st = 128; st > 0; st >>= 1) {
        if (threadIdx.x < st) red[threadIdx.x] += red[threadIdx.x + st];
        __syncthreads();
    }
    const float inv = 1.f / fmaxf(sqrtf(red[0]), 1e-12f);
    for (int c = threadIdx.x * 2; c < Cc; c += 512) {
        __half2 h = __floats2half2_rn(p[c] * inv, p[c + 1] * inv);
        *(uint32_t*)&zh[(long)row * Cc + c] = *(uint32_t*)&h;
    }
}

// ---------------- tensor-core attention --------------------------------------
__global__ __launch_bounds__(256) void attn_tc(
    const __half* __restrict__ qh, const __half* __restrict__ kvh,
    __half* __restrict__ oh)
{
    const int bh = blockIdx.x;
    const int b = bh / Hh;
    const int h = bh % Hh;
    const int n0 = blockIdx.y * 128;

    __shared__ __align__(128) char smem[32768];
    const uint32_t sq = smem_u32(smem);
    const uint32_t sk = sq + 16384;
    const uint32_t sv = sk + 8192;

    const int tid = threadIdx.x;
    const int wid = tid >> 5;
    const int lane = tid & 31;

#pragma unroll
    for (int it = 0; it < 4; it++) {
        int id = tid + it * 256;
        int row = id >> 3, c = id & 7;
        uint32_t off = row * 128 + (((c ^ row) & 7) << 4);
        CP16(sq + off, qh + (size_t)(b * Nn + n0 + row) * Cc + h * Dd + c * 8);
    }
#pragma unroll
    for (int it = 0; it < 2; it++) {
        int id = tid + it * 256;
        int row = id >> 3, c = id & 7;
        uint32_t off = row * 128 + (((c ^ row) & 7) << 4);
        const size_t base = (size_t)(b * Mm + row) * (2 * Cc) + h * Dd + c * 8;
        CP16(sk + off, kvh + base);
        CP16(sv + off, kvh + base + Cc);
    }
    CP_COMMIT();
    CP_WAIT(0);
    __syncthreads();

    float s[8][4];
#pragma unroll
    for (int t = 0; t < 8; t++)
#pragma unroll
        for (int c = 0; c < 4; c++) s[t][c] = 0.f;

#pragma unroll
    for (int kf = 0; kf < 4; kf++) {
        const int ch = kf * 2 + (lane >> 4);
        uint32_t A[4];
        {
            int row = wid * 16 + (lane & 15);
            LDSM4(A, sq + row * 128 + (((ch ^ row) & 7) << 4));
        }
        uint32_t Bk[4][4];
#pragma unroll
        for (int p = 0; p < 4; p++) {
            int row = p * 16 + (lane & 15);
            LDSM4(Bk[p], sk + row * 128 + (((ch ^ row) & 7) << 4));
        }
#pragma unroll
        for (int nt = 0; nt < 8; nt++)
            MMA_F16(s[nt], A, Bk[nt >> 1][nt & 1], Bk[nt >> 1][(nt & 1) + 2]);
    }

    const float scale = 0.125f;
    float m0 = -1e30f, m1 = -1e30f;
#pragma unroll
    for (int t = 0; t < 8; t++) {
#pragma unroll
        for (int c = 0; c < 4; c++) s[t][c] *= scale;
        m0 = fmaxf(m0, fmaxf(s[t][0], s[t][1]));
        m1 = fmaxf(m1, fmaxf(s[t][2], s[t][3]));
    }
    m0 = fmaxf(m0, __shfl_xor_sync(0xffffffff, m0, 1));
    m0 = fmaxf(m0, __shfl_xor_sync(0xffffffff, m0, 2));
    m1 = fmaxf(m1, __shfl_xor_sync(0xffffffff, m1, 1));
    m1 = fmaxf(m1, __shfl_xor_sync(0xffffffff, m1, 2));

    float l0 = 0.f, l1 = 0.f;
    uint32_t P[4][4];
#pragma unroll
    for (int t = 0; t < 8; t++) {
        float p0 = __expf(s[t][0] - m0);
        float p1 = __expf(s[t][1] - m0);
        float p2 = __expf(s[t][2] - m1);
        float p3 = __expf(s[t][3] - m1);
        l0 += p0 + p1;
        l1 += p2 + p3;
        __half2 h01 = __floats2half2_rn(p0, p1);
        __half2 h23 = __floats2half2_rn(p2, p3);
        P[t >> 1][(t & 1) * 2 + 0] = *(uint32_t*)&h01;
        P[t >> 1][(t & 1) * 2 + 1] = *(uint32_t*)&h23;
    }
    l0 += __shfl_xor_sync(0xffffffff, l0, 1);
    l0 += __shfl_xor_sync(0xffffffff, l0, 2);
    l1 += __shfl_xor_sync(0xffffffff, l1, 1);
    l1 += __shfl_xor_sync(0xffffffff, l1, 2);

    float o[8][4];
#pragma unroll
    for (int t = 0; t < 8; t++)
#pragma unroll
        for (int c = 0; c < 4; c++) o[t][c] = 0.f;

#pragma unroll
    for (int kf = 0; kf < 4; kf++) {
#pragma unroll
        for (int dt = 0; dt < 4; dt++) {
            uint32_t VF[4];
            int row = kf * 16 + (lane & 15);
            int ch = dt * 2 + (lane >> 4);
            LDSM4T(VF, sv + row * 128 + (((ch ^ row) & 7) << 4));
            MMA_F16(o[dt * 2],     P[kf], VF[0], VF[1]);
            MMA_F16(o[dt * 2 + 1], P[kf], VF[2], VF[3]);
        }
    }

    const float inv0 = 1.f / l0, inv1 = 1.f / l1;
    const int r = wid * 16 + (lane >> 2);
    const size_t ob = (size_t)(b * Nn + n0 + r) * Cc + h * Dd;
#pragma unroll
    for (int t = 0; t < 8; t++) {
        const int col = t * 8 + (lane & 3) * 2;
        __half2 h0 = __floats2half2_rn(o[t][0] * inv0, o[t][1] * inv0);
        __half2 h1 = __floats2half2_rn(o[t][2] * inv1, o[t][3] * inv1);
        *(__half2*)(oh + ob + col) = h0;
        *(__half2*)(oh + ob + 8 * Cc + col) = h1;
    }
}

// ---------------------------------------------------------------------------
extern "C" void kernel_launch(void* const* d_in, const int* in_sizes, int n_in,
                              void* d_out, int out_size)
{
    (void)in_sizes; (void)n_in; (void)out_size;
    const float* x  = (const float*)d_in[0];
    const float* Wc = (const float*)d_in[1];
    const float* bc = (const float*)d_in[2];
    const float* Wq = (const float*)d_in[3];
    const float* bq = (const float*)d_in[4];
    const float* Wk = (const float*)d_in[5];
    const float* bk = (const float*)d_in[6];
    const float* Wv = (const float*)d_in[7];
    const float* bv = (const float*)d_in[8];
    const float* Wp = (const float*)d_in[9];
    const float* bp = (const float*)d_in[10];
    float* out = (float*)d_out;

    float *z, *bkv;
    __half *cth, *xh, *qh, *kvh, *oh, *zh, *wh, *wcl;
    cudaGetSymbolAddress((void**)&z,   g_z);
    cudaGetSymbolAddress((void**)&bkv, g_bkv);
    cudaGetSymbolAddress((void**)&cth, g_cth);
    cudaGetSymbolAddress((void**)&xh,  g_xh);
    cudaGetSymbolAddress((void**)&qh,  g_qh);
    cudaGetSymbolAddress((void**)&kvh, g_kvh);
    cudaGetSymbolAddress((void**)&oh,  g_oh);
    cudaGetSymbolAddress((void**)&zh,  g_zh);
    cudaGetSymbolAddress((void**)&wh,  g_wh);
    cudaGetSymbolAddress((void**)&wcl, g_wcl);

    constexpr int SMEM_S128 = 2 * (128 * 64 + 128 * 64);      // 32 KB
    constexpr int SMEM_D64  = 2 * (128 * 64 + 2 * 64 * 64);   // 32 KB
    cudaFuncSetAttribute(gemm_tc<128, 0, false, false>,
        cudaFuncAttributeMaxDynamicSharedMemorySize, SMEM_S128);
    cudaFuncSetAttribute(gemm_tc<128, 0, false, true>,
        cudaFuncAttributeMaxDynamicSharedMemorySize, SMEM_S128);
    cudaFuncSetAttribute(gemm_tc<64, 1, true, true>,
        cudaFuncAttributeMaxDynamicSharedMemorySize, SMEM_D64);

    const int IN = Bb * Nn;   // 32768
    const int IM = Bb * Mm;   // 2048

    // 0. converts: x -> fp16; Wc -> fp16 hi+lo; Wq/Wk/Wv/Wp fused -> fp16
    {
        int n4 = IN * Cc / 4;
        cvt_h<<<(n4 + 255) / 256, 256>>>((const float4*)x, (uint2*)xh, n4);
        n4 = Mm * Cc / 4;
        cvt_hl<<<(n4 + 255) / 256, 256>>>((const float4*)Wc,
            (uint2*)(wh + W_OFF_C), (uint2*)wcl, n4);
        n4 = Cc * Cc / 4;
        cvt_w4<<<dim3((n4 + 255) / 256, 4), 256>>>(
            (const float4*)Wq, (const float4*)Wk, (const float4*)Wv,
            (const float4*)Wp, (uint2*)(wh + W_OFF_Q));
        cudaMemcpyAsync(bkv, bk, Cc * sizeof(float), cudaMemcpyDeviceToDevice);
        cudaMemcpyAsync(bkv + Cc, bv, Cc * sizeof(float), cudaMemcpyDeviceToDevice);
    }

    // 1. cluster logits: ct = sigmoid(x @ Wc^T + bc)/N -> fp16 (2-term)
    gemm_tc<64, 1, true, true><<<dim3(1, IN / 128), 256, SMEM_D64>>>(
        xh, wh + W_OFF_C, wcl, bc, cth, Mm);

    // 2. z[b] = ct[b]^T @ x[b]  (tensor cores, trans loads)
    gemm_ctz<<<dim3(Cc / 128, 1, Bb), 256>>>(cth, xh, z);

    // 3. L2 normalize z rows -> fp16
    l2norm<<<IM, 256>>>(z, zh);

    // 4. Q = x @ Wq^T + bq -> fp16
    gemm_tc<128, 0, false, true><<<dim3(Cc / 128, IN / 128), 256, SMEM_S128>>>(
        xh, wh + W_OFF_Q, nullptr, bq, qh, Cc);

    // 5. fused KV = z @ [Wk|Wv]^T + [bk|bv] -> fp16 (2048 x 1536)
    gemm_tc<128, 0, false, true><<<dim3(2 * Cc / 128, IM / 128), 256, SMEM_S128>>>(
        zh, wh + W_OFF_K, nullptr, bkv, kvh, 2 * Cc);

    // 6. tensor-core attention -> o (fp16)
    attn_tc<<<dim3(Bb * Hh, Nn / 128), 256>>>(qh, kvh, oh);

    // 7. out = o @ Wp^T + bp (fp32 out)
    gemm_tc<128, 0, false, false><<<dim3(Cc / 128, IN / 128), 256, SMEM_S128>>>(
        oh, wh + W_OFF_P, nullptr, bp, out, Cc);
}